// round 11
// baseline (speedup 1.0000x reference)
#include <cuda_runtime.h>
#include <cuda_bf16.h>
#include <math.h>
#include <stdint.h>

typedef unsigned long long ull;

#define T_ 512
#define B_ 64
#define F_ 256
#define H_ 1024
#define C_ 257

// ---------------- scratch ----------------
__device__ float g_gates[(size_t)T_ * H_ * B_ * 4]; // [t][j][b][g]
__device__ float g_hT[(size_t)T_ * H_ * B_];        // [t][j][b] (k_out)
__device__ float g_WXpk[(size_t)128 * F_ * 32];
__device__ float g_FCpk[(size_t)9 * H_ * 32];
__device__ float g_xT[(size_t)T_ * F_ * B_];
// W in mma A-fragment order: [cta128][w8][mt2][kt8][split2][reg4][lane32] u32
__device__ uint32_t g_Wfrag[(size_t)128 * 8 * 2 * 8 * 2 * 4 * 32];
// h in mma B-fragment order: [parity2][w8][kt8][nt8][split2][lane32][rb2] u32
__device__ uint32_t g_hfrag[(size_t)2 * 65536];
__device__ int g_flag[(size_t)T_ * 128];

// ---------------- helpers ----------------
__device__ __forceinline__ ull pkdup(float v) {
    ull r; asm("mov.b64 %0, {%1, %1};" : "=l"(r) : "r"(__float_as_uint(v))); return r;
}
__device__ __forceinline__ void fma2(ull& d, ull a, ull b) {
    asm("fma.rn.f32x2 %0, %1, %2, %0;" : "+l"(d) : "l"(a), "l"(b));
}
__device__ __forceinline__ float lo2(ull v) { return __uint_as_float((unsigned)v); }
__device__ __forceinline__ float hi2(ull v) { return __uint_as_float((unsigned)(v >> 32)); }
__device__ __forceinline__ float sigf(float x) { return 1.0f / (1.0f + expf(-x)); }
__device__ __forceinline__ float tanh_acc(float x) {
    float ax = fabsf(x), e = expf(-2.0f * ax);
    return copysignf((1.0f - e) / (1.0f + e), x);
}
__device__ __forceinline__ uint32_t smem_u32(const void* p) {
    uint32_t a;
    asm("{ .reg .u64 t; cvta.to.shared.u64 t, %1; cvt.u32.u64 %0, t; }" : "=r"(a) : "l"(p));
    return a;
}
__device__ __forceinline__ void cpasync16(uint32_t dst, const void* src) {
    asm volatile("cp.async.cg.shared.global [%0], [%1], 16;" :: "r"(dst), "l"(src));
}
#define CP_COMMIT() asm volatile("cp.async.commit_group;" ::: "memory")
#define CP_WAIT0()  asm volatile("cp.async.wait_group 0;" ::: "memory")
__device__ __forceinline__ void mma_bf16(float& d0, float& d1, float& d2, float& d3,
                                         uint32_t a0, uint32_t a1, uint32_t a2,
                                         uint32_t a3, uint32_t b0, uint32_t b1) {
    asm volatile(
        "mma.sync.aligned.m16n8k16.row.col.f32.bf16.bf16.f32 "
        "{%0,%1,%2,%3},{%4,%5,%6,%7},{%8,%9},{%0,%1,%2,%3};"
        : "+f"(d0), "+f"(d1), "+f"(d2), "+f"(d3)
        : "r"(a0), "r"(a1), "r"(a2), "r"(a3), "r"(b0), "r"(b1));
}
__device__ __forceinline__ uint32_t bfbits(float v) {
    return (uint32_t)__bfloat16_as_ushort(__float2bfloat16(v));
}

// ---------------- prep kernels ----------------
__global__ void prep_wfrag(const float* __restrict__ wf, const float* __restrict__ wi,
                           const float* __restrict__ wo, const float* __restrict__ wc) {
    const int total = 128 << 15;
    for (int idx = blockIdx.x * blockDim.x + threadIdx.x; idx < total;
         idx += gridDim.x * blockDim.x) {
        int lane = idx & 31, reg = (idx >> 5) & 3, split = (idx >> 7) & 1;
        int kt = (idx >> 8) & 7, mt = (idx >> 11) & 1, w = (idx >> 12) & 7;
        int cta = idx >> 15;
        int r = mt * 16 + (lane >> 2) + (reg & 1) * 8;
        int k = w * 128 + kt * 16 + (lane & 3) * 2 + (reg >> 1) * 8;
        int g = r >> 3, jj = r & 7, j = cta * 8 + jj;
        const float* W = (g == 0) ? wf : (g == 1) ? wi : (g == 2) ? wo : wc;
        float v0 = W[(size_t)j * H_ + k], v1 = W[(size_t)j * H_ + k + 1];
        uint32_t word;
        if (split == 0) {
            word = bfbits(v0) | (bfbits(v1) << 16);
        } else {
            float h0 = __bfloat162float(__float2bfloat16(v0));
            float h1 = __bfloat162float(__float2bfloat16(v1));
            word = bfbits(v0 - h0) | (bfbits(v1 - h1) << 16);
        }
        g_Wfrag[idx] = word;
    }
}
__global__ void prep_wx(const float* __restrict__ wf, const float* __restrict__ wi,
                        const float* __restrict__ wo, const float* __restrict__ wc) {
    const int total = 128 * F_ * 32;
    for (int idx = blockIdx.x * blockDim.x + threadIdx.x; idx < total;
         idx += gridDim.x * blockDim.x) {
        int r = idx & 31, k = (idx >> 5) & (F_ - 1), jt = idx >> 13;
        int g = r & 3, jj = r >> 2, j = jt * 8 + jj;
        const float* w = (g == 0) ? wf : (g == 1) ? wi : (g == 2) ? wo : wc;
        g_WXpk[idx] = w[(size_t)j * F_ + k];
    }
}
__global__ void prep_fc(const float* __restrict__ fco_w) {
    const int total = 9 * H_ * 32;
    for (int idx = blockIdx.x * blockDim.x + threadIdx.x; idx < total;
         idx += gridDim.x * blockDim.x) {
        int cc = idx & 31, k = (idx >> 5) & (H_ - 1), ct = idx >> 15;
        int c = ct * 32 + cc;
        g_FCpk[idx] = (c < C_) ? fco_w[(size_t)c * H_ + k] : 0.0f;
    }
}
__global__ void prep_xt(const float* __restrict__ x) {
    const int total = T_ * F_ * B_;
    for (int idx = blockIdx.x * blockDim.x + threadIdx.x; idx < total;
         idx += gridDim.x * blockDim.x) {
        int b = idx & (B_ - 1), k = (idx >> 6) & (F_ - 1), t = idx >> 14;
        g_xT[idx] = x[((size_t)t * B_ + b) * F_ + k];
    }
}
__global__ void prep_zero() {
    int i = blockIdx.x * blockDim.x + threadIdx.x;
    if (i < T_ * 128) g_flag[i] = 0;
}

// ---------------- SIMT GEMM core (known-good) ----------------
template <int NK>
__device__ __forceinline__ void gemm_core(const float4* __restrict__ Ag,
                                          const float4* __restrict__ Bg,
                                          float4 (*sA)[256], float4 (*sB)[512],
                                          ull (&acc)[4][2]) {
    const int tid = threadIdx.x, tn = tid >> 4, tb = tid & 15;
    float4 ra0, ra1, rb0, rb1, rb2, rb3;
    ra0 = Ag[tid]; ra1 = Ag[tid + 128];
    rb0 = Bg[tid]; rb1 = Bg[tid + 128]; rb2 = Bg[tid + 256]; rb3 = Bg[tid + 384];
    sA[0][tid] = ra0; sA[0][tid + 128] = ra1;
    sB[0][tid] = rb0; sB[0][tid + 128] = rb1;
    sB[0][tid + 256] = rb2; sB[0][tid + 384] = rb3;
    __syncthreads();
#pragma unroll 1
    for (int ch = 0; ch < NK; ++ch) {
        const int cur = ch & 1, nxt = cur ^ 1;
        if (ch + 1 < NK) {
            const float4* An = Ag + (size_t)(ch + 1) * 256;
            const float4* Bn = Bg + (size_t)(ch + 1) * 512;
            ra0 = An[tid]; ra1 = An[tid + 128];
            rb0 = Bn[tid]; rb1 = Bn[tid + 128];
            rb2 = Bn[tid + 256]; rb3 = Bn[tid + 384];
        }
        const float4* A = sA[cur];
        const float4* Bv = sB[cur];
#pragma unroll
        for (int kk = 0; kk < 32; ++kk) {
            float4 a = A[kk * 8 + tn];
            const ull* bp = reinterpret_cast<const ull*>(&Bv[kk * 16 + tb]);
            ull b0 = bp[0], b1 = bp[1];
            ull a0 = pkdup(a.x), a1 = pkdup(a.y), a2 = pkdup(a.z), a3 = pkdup(a.w);
            fma2(acc[0][0], a0, b0); fma2(acc[0][1], a0, b1);
            fma2(acc[1][0], a1, b0); fma2(acc[1][1], a1, b1);
            fma2(acc[2][0], a2, b0); fma2(acc[2][1], a2, b1);
            fma2(acc[3][0], a3, b0); fma2(acc[3][1], a3, b1);
        }
        __syncthreads();
        if (ch + 1 < NK) {
            sA[nxt][tid] = ra0; sA[nxt][tid + 128] = ra1;
            sB[nxt][tid] = rb0; sB[nxt][tid + 128] = rb1;
            sB[nxt][tid + 256] = rb2; sB[nxt][tid + 384] = rb3;
            __syncthreads();
        }
    }
}
__device__ __forceinline__ void unpack_acc(const ull (&acc)[4][2], float (&z)[4][4]) {
#pragma unroll
    for (int r = 0; r < 4; ++r) {
        z[r][0] = lo2(acc[r][0]); z[r][1] = hi2(acc[r][0]);
        z[r][2] = lo2(acc[r][1]); z[r][3] = hi2(acc[r][1]);
    }
}

__global__ void k_gates(const float* __restrict__ bf, const float* __restrict__ bi,
                        const float* __restrict__ bo, const float* __restrict__ bc) {
    const int jt = blockIdx.x, t = blockIdx.y;
    __shared__ float4 sA[2][256];
    __shared__ float4 sB[2][512];
    ull acc[4][2] = {};
    const float4* Ag = reinterpret_cast<const float4*>(g_WXpk) + (size_t)jt * F_ * 8;
    const float4* Bg = reinterpret_cast<const float4*>(g_xT) + (size_t)t * F_ * 16;
    gemm_core<F_ / 32>(Ag, Bg, sA, sB, acc);
    const int tn = threadIdx.x >> 4, tb = threadIdx.x & 15, j = jt * 8 + tn;
    float z[4][4];
    unpack_acc(acc, z);
    const float b0 = bf[j], b1 = bi[j], b2 = bo[j], b3 = bc[j];
    float4* G = reinterpret_cast<float4*>(g_gates) + ((size_t)t * H_ + j) * 64 + tb * 4;
#pragma unroll
    for (int bb = 0; bb < 4; ++bb)
        G[bb] = make_float4(z[0][bb] + b0, z[1][bb] + b1, z[2][bb] + b2, z[3][bb] + b3);
}

// ---------------- persistent mma.sync recurrence ----------------
// 128 CTAs x 256 thr (8 warps). CTA owns j = cta*8..+7 (32 gate-rows).
// Warp w owns K-slice w*128..+127; A frags register-resident all 512 steps.
// B (h image) staged per-kt through a 2x32KB cp.async double buffer.
#define SM_BUF0 0
#define SM_BUF1 32768
#define SM_PART 65536    // 64 KB: [w][mt][nt][lane][reg] f32
#define SM_ZBUF 131072   // 32 x 66 f32
#define REC_SMEM (131072 + 32 * 66 * 4)

__global__ void __launch_bounds__(256, 1) k_rec3() {
    extern __shared__ unsigned char sm[];
    float* part = reinterpret_cast<float*>(sm + SM_PART);
    float* zbuf = reinterpret_cast<float*>(sm + SM_ZBUF);
    const uint32_t sb = smem_u32(sm);

    const int tid = threadIdx.x, w = tid >> 5, lane = tid & 31;
    const int cta = blockIdx.x;

    // Load A fragments (held in registers for all 512 steps).
    uint32_t A[2][8][2][4];  // [mt][kt][split][reg]
    {
        const uint32_t* src = g_Wfrag + ((size_t)cta * 8 + w) * 4096 + lane;
#pragma unroll
        for (int mt = 0; mt < 2; ++mt)
#pragma unroll
            for (int kt = 0; kt < 8; ++kt)
#pragma unroll
                for (int sp = 0; sp < 2; ++sp)
#pragma unroll
                    for (int rg = 0; rg < 4; ++rg)
                        A[mt][kt][sp][rg] =
                            src[((((mt * 8 + kt) * 2 + sp) * 4 + rg) << 5)];
    }

    const int jj = tid >> 5;            // epilogue row (0..7)
    const int b0 = (tid & 31) * 2;      // epilogue batch pair
    const int j = cta * 8 + jj;
    float cst0 = 0.f, cst1 = 0.f;
    const int w_j = j >> 7, kt_j = (j >> 4) & 7, rb_j = (j >> 3) & 1;
    const int byte_in = (j & 1) * 2;
    const int l_j0 = ((b0 & 7) << 2) + ((j & 7) >> 1);
    const int l_j1 = (((b0 + 1) & 7) << 2) + ((j & 7) >> 1);

#pragma unroll 1
    for (int t = 0; t < T_; ++t) {
        // Gates prefetch (flag-independent) before the wait.
        const float4* G4 = reinterpret_cast<const float4*>(g_gates) +
                           ((size_t)t * H_ + j) * 64 + b0;
        float4 gx0 = G4[0], gx1 = G4[1];

        float zadd[4][2];
        if (t > 0) {
            if (tid < 128) {
                const int* f = g_flag + (t - 1) * 128 + tid;
                int v;
                do {
                    asm volatile("ld.volatile.global.s32 %0, [%1];" : "=r"(v) : "l"(f));
                } while (!v);
            }
            __syncthreads();

            const uint8_t* himg = reinterpret_cast<const uint8_t*>(
                g_hfrag + (size_t)((t - 1) & 1) * 65536);

            float D[2][8][4];
#pragma unroll
            for (int mt = 0; mt < 2; ++mt)
#pragma unroll
                for (int nt = 0; nt < 8; ++nt)
#pragma unroll
                    for (int rg = 0; rg < 4; ++rg) D[mt][nt][rg] = 0.f;

            // Stage kt=0 into buf0.
#pragma unroll
            for (int i = 0; i < 8; ++i) {
                int c = tid + (i << 8);
                int w8 = c >> 8, inner = (c & 255) << 4;
                cpasync16(sb + SM_BUF0 + (c << 4), himg + ((w8 * 8 + 0) << 12) + inner);
            }
            CP_COMMIT();

#pragma unroll 1
            for (int kt = 0; kt < 8; ++kt) {
                CP_WAIT0();
                __syncthreads();  // kt data visible; buf[(kt+1)&1] reads done
                if (kt < 7) {
                    uint32_t dst = sb + (((kt + 1) & 1) ? SM_BUF1 : SM_BUF0);
#pragma unroll
                    for (int i = 0; i < 8; ++i) {
                        int c = tid + (i << 8);
                        int w8 = c >> 8, inner = (c & 255) << 4;
                        cpasync16(dst + (c << 4),
                                  himg + ((w8 * 8 + kt + 1) << 12) + inner);
                    }
                    CP_COMMIT();
                }
                const uint32_t* bw = reinterpret_cast<const uint32_t*>(
                                         sm + ((kt & 1) ? SM_BUF1 : SM_BUF0)) +
                                     (w << 10);
#pragma unroll
                for (int nt = 0; nt < 8; ++nt) {
                    uint2 bh = *reinterpret_cast<const uint2*>(bw + nt * 128 + lane * 2);
                    uint2 bl = *reinterpret_cast<const uint2*>(bw + nt * 128 + 64 +
                                                               lane * 2);
#pragma unroll
                    for (int mt = 0; mt < 2; ++mt) {
                        mma_bf16(D[mt][nt][0], D[mt][nt][1], D[mt][nt][2], D[mt][nt][3],
                                 A[mt][kt][0][0], A[mt][kt][0][1], A[mt][kt][0][2],
                                 A[mt][kt][0][3], bh.x, bh.y);
                        mma_bf16(D[mt][nt][0], D[mt][nt][1], D[mt][nt][2], D[mt][nt][3],
                                 A[mt][kt][0][0], A[mt][kt][0][1], A[mt][kt][0][2],
                                 A[mt][kt][0][3], bl.x, bl.y);
                        mma_bf16(D[mt][nt][0], D[mt][nt][1], D[mt][nt][2], D[mt][nt][3],
                                 A[mt][kt][1][0], A[mt][kt][1][1], A[mt][kt][1][2],
                                 A[mt][kt][1][3], bh.x, bh.y);
                    }
                }
            }
            // Store K-partials.
#pragma unroll
            for (int mt = 0; mt < 2; ++mt)
#pragma unroll
                for (int nt = 0; nt < 8; ++nt)
                    *reinterpret_cast<float4*>(
                        part + ((((w * 2 + mt) * 8 + nt) * 32) + lane) * 4) =
                        make_float4(D[mt][nt][0], D[mt][nt][1], D[mt][nt][2],
                                    D[mt][nt][3]);
            __syncthreads();
            // Reduce over 8 warps -> zbuf[r][n].
#pragma unroll
            for (int cc = 0; cc < 2; ++cc) {
                int c = tid + cc * 256;
                int mt = c >> 8, nt = (c >> 5) & 7, ln = c & 31;
                float4 s = make_float4(0.f, 0.f, 0.f, 0.f);
#pragma unroll
                for (int ww = 0; ww < 8; ++ww) {
                    float4 p = *reinterpret_cast<const float4*>(
                        part + ((((ww * 2 + mt) * 8 + nt) * 32) + ln) * 4);
                    s.x += p.x; s.y += p.y; s.z += p.z; s.w += p.w;
                }
                int r = mt * 16 + (ln >> 2);
                int n = nt * 8 + (ln & 3) * 2;
                *reinterpret_cast<float2*>(zbuf + r * 66 + n) = make_float2(s.x, s.y);
                *reinterpret_cast<float2*>(zbuf + (r + 8) * 66 + n) =
                    make_float2(s.z, s.w);
            }
            __syncthreads();
#pragma unroll
            for (int g = 0; g < 4; ++g) {
                float2 v = *reinterpret_cast<const float2*>(zbuf + (g * 8 + jj) * 66 + b0);
                zadd[g][0] = v.x;
                zadd[g][1] = v.y;
            }
            __syncthreads();
        } else {
#pragma unroll
            for (int g = 0; g < 4; ++g) zadd[g][0] = zadd[g][1] = 0.f;
        }

        // LSTM cell: 2 cells (j, b0) and (j, b0+1).
        float ft0 = sigf(gx0.x + zadd[0][0]), it0 = sigf(gx0.y + zadd[1][0]);
        float ot0 = sigf(gx0.z + zadd[2][0]);
        cst0 = it0 * tanh_acc(gx0.w + zadd[3][0]) + ft0 * cst0;
        float h0 = ot0 * tanh_acc(cst0);
        float ft1 = sigf(gx1.x + zadd[0][1]), it1 = sigf(gx1.y + zadd[1][1]);
        float ot1 = sigf(gx1.z + zadd[2][1]);
        cst1 = it1 * tanh_acc(gx1.w + zadd[3][1]) + ft1 * cst1;
        float h1 = ot1 * tanh_acc(cst1);

        *reinterpret_cast<float2*>(g_hT + ((size_t)t * H_ + j) * B_ + b0) =
            make_float2(h0, h1);
        {
            uint32_t* img = g_hfrag + (size_t)(t & 1) * 65536;
            const int nt = b0 >> 3;
            size_t base = (((w_j * 8 + kt_j) * 8 + nt) * 2) * 64;
            unsigned char* pH0 = (unsigned char*)(img + base + l_j0 * 2 + rb_j) + byte_in;
            unsigned char* pH1 = (unsigned char*)(img + base + l_j1 * 2 + rb_j) + byte_in;
            unsigned char* pL0 = pH0 + 64 * 4;
            unsigned char* pL1 = pH1 + 64 * 4;
            __nv_bfloat16 h0h = __float2bfloat16(h0);
            __nv_bfloat16 h1h = __float2bfloat16(h1);
            *(__nv_bfloat16*)pH0 = h0h;
            *(__nv_bfloat16*)pH1 = h1h;
            *(__nv_bfloat16*)pL0 = __float2bfloat16(h0 - __bfloat162float(h0h));
            *(__nv_bfloat16*)pL1 = __float2bfloat16(h1 - __bfloat162float(h1h));
        }
        __threadfence();
        __syncthreads();
        if (tid == 0) {
            asm volatile("st.volatile.global.s32 [%0], %1;"
                         :: "l"(g_flag + t * 128 + cta), "r"(1) : "memory");
        }
    }
}

// ---------------- output projection ----------------
__global__ void k_out(const float* __restrict__ fco_b, float* __restrict__ out) {
    const int ct = blockIdx.x, t = blockIdx.y;
    __shared__ float4 sA[2][256];
    __shared__ float4 sB[2][512];
    ull acc[4][2] = {};
    const float4* Ag = reinterpret_cast<const float4*>(g_FCpk) + (size_t)ct * H_ * 8;
    const float4* Bg = reinterpret_cast<const float4*>(g_hT) + (size_t)t * H_ * 16;
    gemm_core<H_ / 32>(Ag, Bg, sA, sB, acc);
    const int tn = threadIdx.x >> 4, tb = threadIdx.x & 15, c0 = ct * 32 + tn * 4;
    float z[4][4];
    unpack_acc(acc, z);
#pragma unroll
    for (int bb = 0; bb < 4; ++bb) {
        const int b = tb * 4 + bb;
        float* o = out + ((size_t)t * B_ + b) * C_;
#pragma unroll
        for (int ci = 0; ci < 4; ++ci) {
            const int c = c0 + ci;
            if (c < C_) o[c] = z[ci][bb] + fco_b[c];
        }
    }
}

// ---------------- launch ----------------
extern "C" void kernel_launch(void* const* d_in, const int* in_sizes, int n_in,
                              void* d_out, int out_size) {
    const float* x     = (const float*)d_in[0];
    const float* wfx_w = (const float*)d_in[1];
    const float* wfx_b = (const float*)d_in[2];
    const float* wix_w = (const float*)d_in[3];
    const float* wix_b = (const float*)d_in[4];
    const float* wox_w = (const float*)d_in[5];
    const float* wox_b = (const float*)d_in[6];
    const float* wcx_w = (const float*)d_in[7];
    const float* wcx_b = (const float*)d_in[8];
    const float* wfh_w = (const float*)d_in[9];
    const float* wih_w = (const float*)d_in[10];
    const float* woh_w = (const float*)d_in[11];
    const float* wch_w = (const float*)d_in[12];
    const float* fco_w = (const float*)d_in[13];
    const float* fco_b = (const float*)d_in[14];
    float* out = (float*)d_out;
    (void)in_sizes; (void)n_in; (void)out_size;

    cudaFuncSetAttribute(k_rec3, cudaFuncAttributeMaxDynamicSharedMemorySize,
                         REC_SMEM);

    prep_wfrag<<<8192, 256>>>(wfh_w, wih_w, woh_w, wch_w);
    prep_wx<<<2048, 256>>>(wfx_w, wix_w, wox_w, wcx_w);
    prep_fc<<<576, 256>>>(fco_w);
    prep_xt<<<4096, 256>>>(x);
    prep_zero<<<256, 256>>>();

    k_gates<<<dim3(128, 512), 128>>>(wfx_b, wix_b, wox_b, wcx_b);

    k_rec3<<<128, 256, REC_SMEM>>>();

    k_out<<<dim3(9, 512), 128>>>(fco_b, out);
}

// round 12
// speedup vs baseline: 1.1665x; 1.1665x over previous
#include <cuda_runtime.h>
#include <cuda_bf16.h>
#include <math.h>
#include <stdint.h>

typedef unsigned long long ull;

#define T_ 512
#define B_ 64
#define F_ 256
#define H_ 1024
#define C_ 257

// ---------------- scratch ----------------
__device__ float g_gates[(size_t)T_ * H_ * B_ * 4]; // [t][j][b][g]
__device__ float g_hT[(size_t)T_ * H_ * B_];        // [t][j][b] (k_out)
__device__ float g_WXpk[(size_t)128 * F_ * 32];
__device__ float g_FCpk[(size_t)9 * H_ * 32];
__device__ float g_xT[(size_t)T_ * F_ * B_];
// W in mma A-fragment order: [cta128][w8][mt2][kt8][split2][reg4][lane32] u32
__device__ uint32_t g_Wfrag[(size_t)128 * 8 * 2 * 8 * 2 * 4 * 32];
// h in mma B-fragment order: [parity2][w8][kt8][nt8][split2][lane32][rb2] u32
__device__ uint32_t g_hfrag[(size_t)2 * 65536];
__device__ int g_flag[(size_t)T_ * 128];

// ---------------- helpers ----------------
__device__ __forceinline__ ull pkdup(float v) {
    ull r; asm("mov.b64 %0, {%1, %1};" : "=l"(r) : "r"(__float_as_uint(v))); return r;
}
__device__ __forceinline__ void fma2(ull& d, ull a, ull b) {
    asm("fma.rn.f32x2 %0, %1, %2, %0;" : "+l"(d) : "l"(a), "l"(b));
}
__device__ __forceinline__ float lo2(ull v) { return __uint_as_float((unsigned)v); }
__device__ __forceinline__ float hi2(ull v) { return __uint_as_float((unsigned)(v >> 32)); }
__device__ __forceinline__ float sigf(float x) { return 1.0f / (1.0f + expf(-x)); }
__device__ __forceinline__ float tanh_acc(float x) {
    float ax = fabsf(x), e = expf(-2.0f * ax);
    return copysignf((1.0f - e) / (1.0f + e), x);
}
__device__ __forceinline__ uint2 ldg_cg2(const uint32_t* p) {
    uint2 v;
    asm volatile("ld.global.cg.v2.u32 {%0,%1}, [%2];" : "=r"(v.x), "=r"(v.y) : "l"(p));
    return v;
}
__device__ __forceinline__ void mma_bf16(float& d0, float& d1, float& d2, float& d3,
                                         uint32_t a0, uint32_t a1, uint32_t a2,
                                         uint32_t a3, uint32_t b0, uint32_t b1) {
    asm volatile(
        "mma.sync.aligned.m16n8k16.row.col.f32.bf16.bf16.f32 "
        "{%0,%1,%2,%3},{%4,%5,%6,%7},{%8,%9},{%0,%1,%2,%3};"
        : "+f"(d0), "+f"(d1), "+f"(d2), "+f"(d3)
        : "r"(a0), "r"(a1), "r"(a2), "r"(a3), "r"(b0), "r"(b1));
}
__device__ __forceinline__ uint32_t bfbits(float v) {
    return (uint32_t)__bfloat16_as_ushort(__float2bfloat16(v));
}

// ---------------- prep kernels ----------------
__global__ void prep_wfrag(const float* __restrict__ wf, const float* __restrict__ wi,
                           const float* __restrict__ wo, const float* __restrict__ wc) {
    const int total = 128 << 15;
    for (int idx = blockIdx.x * blockDim.x + threadIdx.x; idx < total;
         idx += gridDim.x * blockDim.x) {
        int lane = idx & 31, reg = (idx >> 5) & 3, split = (idx >> 7) & 1;
        int kt = (idx >> 8) & 7, mt = (idx >> 11) & 1, w = (idx >> 12) & 7;
        int cta = idx >> 15;
        int r = mt * 16 + (lane >> 2) + (reg & 1) * 8;
        int k = w * 128 + kt * 16 + (lane & 3) * 2 + (reg >> 1) * 8;
        int g = r >> 3, jj = r & 7, j = cta * 8 + jj;
        const float* W = (g == 0) ? wf : (g == 1) ? wi : (g == 2) ? wo : wc;
        float v0 = W[(size_t)j * H_ + k], v1 = W[(size_t)j * H_ + k + 1];
        uint32_t word;
        if (split == 0) {
            word = bfbits(v0) | (bfbits(v1) << 16);
        } else {
            float h0 = __bfloat162float(__float2bfloat16(v0));
            float h1 = __bfloat162float(__float2bfloat16(v1));
            word = bfbits(v0 - h0) | (bfbits(v1 - h1) << 16);
        }
        g_Wfrag[idx] = word;
    }
}
__global__ void prep_wx(const float* __restrict__ wf, const float* __restrict__ wi,
                        const float* __restrict__ wo, const float* __restrict__ wc) {
    const int total = 128 * F_ * 32;
    for (int idx = blockIdx.x * blockDim.x + threadIdx.x; idx < total;
         idx += gridDim.x * blockDim.x) {
        int r = idx & 31, k = (idx >> 5) & (F_ - 1), jt = idx >> 13;
        int g = r & 3, jj = r >> 2, j = jt * 8 + jj;
        const float* w = (g == 0) ? wf : (g == 1) ? wi : (g == 2) ? wo : wc;
        g_WXpk[idx] = w[(size_t)j * F_ + k];
    }
}
__global__ void prep_fc(const float* __restrict__ fco_w) {
    const int total = 9 * H_ * 32;
    for (int idx = blockIdx.x * blockDim.x + threadIdx.x; idx < total;
         idx += gridDim.x * blockDim.x) {
        int cc = idx & 31, k = (idx >> 5) & (H_ - 1), ct = idx >> 15;
        int c = ct * 32 + cc;
        g_FCpk[idx] = (c < C_) ? fco_w[(size_t)c * H_ + k] : 0.0f;
    }
}
__global__ void prep_xt(const float* __restrict__ x) {
    const int total = T_ * F_ * B_;
    for (int idx = blockIdx.x * blockDim.x + threadIdx.x; idx < total;
         idx += gridDim.x * blockDim.x) {
        int b = idx & (B_ - 1), k = (idx >> 6) & (F_ - 1), t = idx >> 14;
        g_xT[idx] = x[((size_t)t * B_ + b) * F_ + k];
    }
}
__global__ void prep_zero() {
    int i = blockIdx.x * blockDim.x + threadIdx.x;
    if (i < T_ * 128) g_flag[i] = 0;
}

// ---------------- SIMT GEMM core (known-good) ----------------
template <int NK>
__device__ __forceinline__ void gemm_core(const float4* __restrict__ Ag,
                                          const float4* __restrict__ Bg,
                                          float4 (*sA)[256], float4 (*sB)[512],
                                          ull (&acc)[4][2]) {
    const int tid = threadIdx.x, tn = tid >> 4, tb = tid & 15;
    float4 ra0, ra1, rb0, rb1, rb2, rb3;
    ra0 = Ag[tid]; ra1 = Ag[tid + 128];
    rb0 = Bg[tid]; rb1 = Bg[tid + 128]; rb2 = Bg[tid + 256]; rb3 = Bg[tid + 384];
    sA[0][tid] = ra0; sA[0][tid + 128] = ra1;
    sB[0][tid] = rb0; sB[0][tid + 128] = rb1;
    sB[0][tid + 256] = rb2; sB[0][tid + 384] = rb3;
    __syncthreads();
#pragma unroll 1
    for (int ch = 0; ch < NK; ++ch) {
        const int cur = ch & 1, nxt = cur ^ 1;
        if (ch + 1 < NK) {
            const float4* An = Ag + (size_t)(ch + 1) * 256;
            const float4* Bn = Bg + (size_t)(ch + 1) * 512;
            ra0 = An[tid]; ra1 = An[tid + 128];
            rb0 = Bn[tid]; rb1 = Bn[tid + 128];
            rb2 = Bn[tid + 256]; rb3 = Bn[tid + 384];
        }
        const float4* A = sA[cur];
        const float4* Bv = sB[cur];
#pragma unroll
        for (int kk = 0; kk < 32; ++kk) {
            float4 a = A[kk * 8 + tn];
            const ull* bp = reinterpret_cast<const ull*>(&Bv[kk * 16 + tb]);
            ull b0 = bp[0], b1 = bp[1];
            ull a0 = pkdup(a.x), a1 = pkdup(a.y), a2 = pkdup(a.z), a3 = pkdup(a.w);
            fma2(acc[0][0], a0, b0); fma2(acc[0][1], a0, b1);
            fma2(acc[1][0], a1, b0); fma2(acc[1][1], a1, b1);
            fma2(acc[2][0], a2, b0); fma2(acc[2][1], a2, b1);
            fma2(acc[3][0], a3, b0); fma2(acc[3][1], a3, b1);
        }
        __syncthreads();
        if (ch + 1 < NK) {
            sA[nxt][tid] = ra0; sA[nxt][tid + 128] = ra1;
            sB[nxt][tid] = rb0; sB[nxt][tid + 128] = rb1;
            sB[nxt][tid + 256] = rb2; sB[nxt][tid + 384] = rb3;
            __syncthreads();
        }
    }
}
__device__ __forceinline__ void unpack_acc(const ull (&acc)[4][2], float (&z)[4][4]) {
#pragma unroll
    for (int r = 0; r < 4; ++r) {
        z[r][0] = lo2(acc[r][0]); z[r][1] = hi2(acc[r][0]);
        z[r][2] = lo2(acc[r][1]); z[r][3] = hi2(acc[r][1]);
    }
}

__global__ void k_gates(const float* __restrict__ bf, const float* __restrict__ bi,
                        const float* __restrict__ bo, const float* __restrict__ bc) {
    const int jt = blockIdx.x, t = blockIdx.y;
    __shared__ float4 sA[2][256];
    __shared__ float4 sB[2][512];
    ull acc[4][2] = {};
    const float4* Ag = reinterpret_cast<const float4*>(g_WXpk) + (size_t)jt * F_ * 8;
    const float4* Bg = reinterpret_cast<const float4*>(g_xT) + (size_t)t * F_ * 16;
    gemm_core<F_ / 32>(Ag, Bg, sA, sB, acc);
    const int tn = threadIdx.x >> 4, tb = threadIdx.x & 15, j = jt * 8 + tn;
    float z[4][4];
    unpack_acc(acc, z);
    const float b0 = bf[j], b1 = bi[j], b2 = bo[j], b3 = bc[j];
    float4* G = reinterpret_cast<float4*>(g_gates) + ((size_t)t * H_ + j) * 64 + tb * 4;
#pragma unroll
    for (int bb = 0; bb < 4; ++bb)
        G[bb] = make_float4(z[0][bb] + b0, z[1][bb] + b1, z[2][bb] + b2, z[3][bb] + b3);
}

// ---------------- persistent mma.sync recurrence ----------------
// 128 CTAs x 256 thr (8 warps). CTA owns j = cta*8..+7 (32 gate-rows).
// Warp w owns K-slice w*128..+127; A frags register-resident all 512 steps.
// Release protocol: stores -> __syncthreads -> tid0 st.release.gpu flag;
// consumers poll ld.acquire.gpu (CG grid-sync pattern; cumulativity via bar).
#define SM_PART 0        // 64 KB: [w][mt][nt][lane][reg] f32
#define SM_ZBUF 65536    // 32 x 66 f32
#define REC_SMEM (65536 + 32 * 66 * 4)

__global__ void __launch_bounds__(256, 1) k_rec3() {
    extern __shared__ unsigned char sm[];
    float* part = reinterpret_cast<float*>(sm + SM_PART);
    float* zbuf = reinterpret_cast<float*>(sm + SM_ZBUF);

    const int tid = threadIdx.x, w = tid >> 5, lane = tid & 31;
    const int cta = blockIdx.x;

    // Load A fragments (held in registers for all 512 steps).
    uint32_t A[2][8][2][4];  // [mt][kt][split][reg]
    {
        const uint32_t* src = g_Wfrag + ((size_t)cta * 8 + w) * 4096 + lane;
#pragma unroll
        for (int mt = 0; mt < 2; ++mt)
#pragma unroll
            for (int kt = 0; kt < 8; ++kt)
#pragma unroll
                for (int sp = 0; sp < 2; ++sp)
#pragma unroll
                    for (int rg = 0; rg < 4; ++rg)
                        A[mt][kt][sp][rg] =
                            src[((((mt * 8 + kt) * 2 + sp) * 4 + rg) << 5)];
    }

    const int jj = tid >> 5;            // epilogue row (0..7)
    const int b0 = (tid & 31) * 2;      // epilogue batch pair
    const int j = cta * 8 + jj;
    float cst0 = 0.f, cst1 = 0.f;
    const int w_j = j >> 7, kt_j = (j >> 4) & 7, rb_j = (j >> 3) & 1;
    const int byte_in = (j & 1) * 2;
    const int l_j0 = ((b0 & 7) << 2) + ((j & 7) >> 1);
    const int l_j1 = (((b0 + 1) & 7) << 2) + ((j & 7) >> 1);

#pragma unroll 1
    for (int t = 0; t < T_; ++t) {
        // Gates prefetch (flag-independent) before the wait.
        const float4* G4 = reinterpret_cast<const float4*>(g_gates) +
                           ((size_t)t * H_ + j) * 64 + b0;
        float4 gx0 = G4[0], gx1 = G4[1];

        float zadd[4][2];
        if (t > 0) {
            if (tid < 128) {
                const int* f = g_flag + (t - 1) * 128 + tid;
                int v;
                do {
                    asm volatile("ld.acquire.gpu.global.b32 %0, [%1];"
                                 : "=r"(v) : "l"(f));
                } while (!v);
            }
            __syncthreads();

            float D[2][8][4];
#pragma unroll
            for (int mt = 0; mt < 2; ++mt)
#pragma unroll
                for (int nt = 0; nt < 8; ++nt)
#pragma unroll
                    for (int rg = 0; rg < 4; ++rg) D[mt][nt][rg] = 0.f;

            const uint32_t* himg = g_hfrag + (size_t)((t - 1) & 1) * 65536;
#pragma unroll
            for (int kt = 0; kt < 8; ++kt) {
#pragma unroll
                for (int nt = 0; nt < 8; ++nt) {
                    const uint32_t* bb =
                        himg + (((w * 8 + kt) * 8 + nt) * 2) * 64 + lane * 2;
                    uint2 bh = ldg_cg2(bb);
                    uint2 bl = ldg_cg2(bb + 64);
#pragma unroll
                    for (int mt = 0; mt < 2; ++mt) {
                        mma_bf16(D[mt][nt][0], D[mt][nt][1], D[mt][nt][2], D[mt][nt][3],
                                 A[mt][kt][0][0], A[mt][kt][0][1], A[mt][kt][0][2],
                                 A[mt][kt][0][3], bh.x, bh.y);
                        mma_bf16(D[mt][nt][0], D[mt][nt][1], D[mt][nt][2], D[mt][nt][3],
                                 A[mt][kt][0][0], A[mt][kt][0][1], A[mt][kt][0][2],
                                 A[mt][kt][0][3], bl.x, bl.y);
                        mma_bf16(D[mt][nt][0], D[mt][nt][1], D[mt][nt][2], D[mt][nt][3],
                                 A[mt][kt][1][0], A[mt][kt][1][1], A[mt][kt][1][2],
                                 A[mt][kt][1][3], bh.x, bh.y);
                    }
                }
            }
            // Store K-partials.
#pragma unroll
            for (int mt = 0; mt < 2; ++mt)
#pragma unroll
                for (int nt = 0; nt < 8; ++nt)
                    *reinterpret_cast<float4*>(
                        part + ((((w * 2 + mt) * 8 + nt) * 32) + lane) * 4) =
                        make_float4(D[mt][nt][0], D[mt][nt][1], D[mt][nt][2],
                                    D[mt][nt][3]);
            __syncthreads();
            // Reduce over 8 warps -> zbuf[r][n].
#pragma unroll
            for (int cc = 0; cc < 2; ++cc) {
                int c = tid + cc * 256;
                int mt = c >> 8, nt = (c >> 5) & 7, ln = c & 31;
                float4 s = make_float4(0.f, 0.f, 0.f, 0.f);
#pragma unroll
                for (int ww = 0; ww < 8; ++ww) {
                    float4 p = *reinterpret_cast<const float4*>(
                        part + ((((ww * 2 + mt) * 8 + nt) * 32) + ln) * 4);
                    s.x += p.x; s.y += p.y; s.z += p.z; s.w += p.w;
                }
                int r = mt * 16 + (ln >> 2);
                int n = nt * 8 + (ln & 3) * 2;
                *reinterpret_cast<float2*>(zbuf + r * 66 + n) = make_float2(s.x, s.y);
                *reinterpret_cast<float2*>(zbuf + (r + 8) * 66 + n) =
                    make_float2(s.z, s.w);
            }
            __syncthreads();
#pragma unroll
            for (int g = 0; g < 4; ++g) {
                float2 v = *reinterpret_cast<const float2*>(zbuf + (g * 8 + jj) * 66 + b0);
                zadd[g][0] = v.x;
                zadd[g][1] = v.y;
            }
            // zbuf reads complete before the release barrier below; next
            // step's part/zbuf writes are ordered after it.
        } else {
#pragma unroll
            for (int g = 0; g < 4; ++g) zadd[g][0] = zadd[g][1] = 0.f;
        }

        // LSTM cell: 2 cells (j, b0) and (j, b0+1).
        float ft0 = sigf(gx0.x + zadd[0][0]), it0 = sigf(gx0.y + zadd[1][0]);
        float ot0 = sigf(gx0.z + zadd[2][0]);
        cst0 = it0 * tanh_acc(gx0.w + zadd[3][0]) + ft0 * cst0;
        float h0 = ot0 * tanh_acc(cst0);
        float ft1 = sigf(gx1.x + zadd[0][1]), it1 = sigf(gx1.y + zadd[1][1]);
        float ot1 = sigf(gx1.z + zadd[2][1]);
        cst1 = it1 * tanh_acc(gx1.w + zadd[3][1]) + ft1 * cst1;
        float h1 = ot1 * tanh_acc(cst1);

        *reinterpret_cast<float2*>(g_hT + ((size_t)t * H_ + j) * B_ + b0) =
            make_float2(h0, h1);
        {
            uint32_t* img = g_hfrag + (size_t)(t & 1) * 65536;
            const int nt = b0 >> 3;
            size_t base = (((w_j * 8 + kt_j) * 8 + nt) * 2) * 64;
            unsigned char* pH0 = (unsigned char*)(img + base + l_j0 * 2 + rb_j) + byte_in;
            unsigned char* pH1 = (unsigned char*)(img + base + l_j1 * 2 + rb_j) + byte_in;
            unsigned char* pL0 = pH0 + 64 * 4;
            unsigned char* pL1 = pH1 + 64 * 4;
            __nv_bfloat16 h0h = __float2bfloat16(h0);
            __nv_bfloat16 h1h = __float2bfloat16(h1);
            *(__nv_bfloat16*)pH0 = h0h;
            *(__nv_bfloat16*)pH1 = h1h;
            *(__nv_bfloat16*)pL0 = __float2bfloat16(h0 - __bfloat162float(h0h));
            *(__nv_bfloat16*)pL1 = __float2bfloat16(h1 - __bfloat162float(h1h));
        }
        // Release: barrier gives CTA-scope happens-before into tid0; the
        // release store publishes all threads' stores at gpu scope.
        __syncthreads();
        if (tid == 0) {
            asm volatile("st.release.gpu.global.b32 [%0], %1;"
                         :: "l"(g_flag + t * 128 + cta), "r"(1) : "memory");
        }
    }
}

// ---------------- output projection ----------------
__global__ void k_out(const float* __restrict__ fco_b, float* __restrict__ out) {
    const int ct = blockIdx.x, t = blockIdx.y;
    __shared__ float4 sA[2][256];
    __shared__ float4 sB[2][512];
    ull acc[4][2] = {};
    const float4* Ag = reinterpret_cast<const float4*>(g_FCpk) + (size_t)ct * H_ * 8;
    const float4* Bg = reinterpret_cast<const float4*>(g_hT) + (size_t)t * H_ * 16;
    gemm_core<H_ / 32>(Ag, Bg, sA, sB, acc);
    const int tn = threadIdx.x >> 4, tb = threadIdx.x & 15, c0 = ct * 32 + tn * 4;
    float z[4][4];
    unpack_acc(acc, z);
#pragma unroll
    for (int bb = 0; bb < 4; ++bb) {
        const int b = tb * 4 + bb;
        float* o = out + ((size_t)t * B_ + b) * C_;
#pragma unroll
        for (int ci = 0; ci < 4; ++ci) {
            const int c = c0 + ci;
            if (c < C_) o[c] = z[ci][bb] + fco_b[c];
        }
    }
}

// ---------------- launch ----------------
extern "C" void kernel_launch(void* const* d_in, const int* in_sizes, int n_in,
                              void* d_out, int out_size) {
    const float* x     = (const float*)d_in[0];
    const float* wfx_w = (const float*)d_in[1];
    const float* wfx_b = (const float*)d_in[2];
    const float* wix_w = (const float*)d_in[3];
    const float* wix_b = (const float*)d_in[4];
    const float* wox_w = (const float*)d_in[5];
    const float* wox_b = (const float*)d_in[6];
    const float* wcx_w = (const float*)d_in[7];
    const float* wcx_b = (const float*)d_in[8];
    const float* wfh_w = (const float*)d_in[9];
    const float* wih_w = (const float*)d_in[10];
    const float* woh_w = (const float*)d_in[11];
    const float* wch_w = (const float*)d_in[12];
    const float* fco_w = (const float*)d_in[13];
    const float* fco_b = (const float*)d_in[14];
    float* out = (float*)d_out;
    (void)in_sizes; (void)n_in; (void)out_size;

    cudaFuncSetAttribute(k_rec3, cudaFuncAttributeMaxDynamicSharedMemorySize,
                         REC_SMEM);

    prep_wfrag<<<8192, 256>>>(wfh_w, wih_w, woh_w, wch_w);
    prep_wx<<<2048, 256>>>(wfx_w, wix_w, wox_w, wcx_w);
    prep_fc<<<576, 256>>>(fco_w);
    prep_xt<<<4096, 256>>>(x);
    prep_zero<<<256, 256>>>();

    k_gates<<<dim3(128, 512), 128>>>(wfx_b, wix_b, wox_b, wcx_b);

    k_rec3<<<128, 256, REC_SMEM>>>();

    k_out<<<dim3(9, 512), 128>>>(fco_b, out);
}

// round 14
// speedup vs baseline: 1.2062x; 1.0340x over previous
#include <cuda_runtime.h>
#include <cuda_bf16.h>
#include <math.h>
#include <stdint.h>

typedef unsigned long long ull;

#define T_ 512
#define B_ 64
#define F_ 256
#define H_ 1024
#define C_ 257

// ---------------- scratch ----------------
__device__ float g_gates[(size_t)T_ * H_ * B_ * 4]; // [t][j][b][g]
__device__ float g_hT[(size_t)T_ * H_ * B_];        // [t][j][b] (k_out)
__device__ float g_FCpk[(size_t)9 * H_ * 32];
// W (recurrent) in mma A-frag order: [cta][w8][mt2][kt8][split2][reg4][lane32]
__device__ uint32_t g_Wfrag[(size_t)128 * 8 * 2 * 8 * 2 * 4 * 32];
// Wx (input) in mma A-frag order: [cta][w8][mt2][kt2][split2][reg4][lane32]
__device__ uint32_t g_WXfrag[(size_t)128 * 8 * 2 * 2 * 2 * 4 * 32];
// h in mma B-frag order: [parity2][w8][kt8][nt8][split2][lane32][rb2]
__device__ uint32_t g_hfrag[(size_t)2 * 65536];
// x in mma B-frag order: [t][w8][kt2][nt8][split2][lane32][rb2] = 16384 u32/t
__device__ uint32_t g_xfrag[(size_t)T_ * 16384];
__device__ int g_flag[(size_t)T_ * 128];

// ---------------- helpers ----------------
__device__ __forceinline__ ull pkdup(float v) {
    ull r; asm("mov.b64 %0, {%1, %1};" : "=l"(r) : "r"(__float_as_uint(v))); return r;
}
__device__ __forceinline__ void fma2(ull& d, ull a, ull b) {
    asm("fma.rn.f32x2 %0, %1, %2, %0;" : "+l"(d) : "l"(a), "l"(b));
}
__device__ __forceinline__ float lo2(ull v) { return __uint_as_float((unsigned)v); }
__device__ __forceinline__ float hi2(ull v) { return __uint_as_float((unsigned)(v >> 32)); }
__device__ __forceinline__ float sigf(float x) { return 1.0f / (1.0f + expf(-x)); }
__device__ __forceinline__ float tanh_acc(float x) {
    float ax = fabsf(x), e = expf(-2.0f * ax);
    return copysignf((1.0f - e) / (1.0f + e), x);
}
__device__ __forceinline__ uint2 ldg_cg2(const uint32_t* p) {
    uint2 v;
    asm volatile("ld.global.cg.v2.u32 {%0,%1}, [%2];" : "=r"(v.x), "=r"(v.y) : "l"(p));
    return v;
}
__device__ __forceinline__ void mma_bf16(float& d0, float& d1, float& d2, float& d3,
                                         uint32_t a0, uint32_t a1, uint32_t a2,
                                         uint32_t a3, uint32_t b0, uint32_t b1) {
    asm volatile(
        "mma.sync.aligned.m16n8k16.row.col.f32.bf16.bf16.f32 "
        "{%0,%1,%2,%3},{%4,%5,%6,%7},{%8,%9},{%0,%1,%2,%3};"
        : "+f"(d0), "+f"(d1), "+f"(d2), "+f"(d3)
        : "r"(a0), "r"(a1), "r"(a2), "r"(a3), "r"(b0), "r"(b1));
}
__device__ __forceinline__ uint32_t bfbits(float v) {
    return (uint32_t)__bfloat16_as_ushort(__float2bfloat16(v));
}
__device__ __forceinline__ uint32_t split_word(float v0, float v1, int split) {
    if (split == 0) return bfbits(v0) | (bfbits(v1) << 16);
    float h0 = __bfloat162float(__float2bfloat16(v0));
    float h1 = __bfloat162float(__float2bfloat16(v1));
    return bfbits(v0 - h0) | (bfbits(v1 - h1) << 16);
}

// ---------------- prep kernels ----------------
__global__ void prep_wfrag(const float* __restrict__ wf, const float* __restrict__ wi,
                           const float* __restrict__ wo, const float* __restrict__ wc) {
    const int total = 128 << 15;
    for (int idx = blockIdx.x * blockDim.x + threadIdx.x; idx < total;
         idx += gridDim.x * blockDim.x) {
        int lane = idx & 31, reg = (idx >> 5) & 3, split = (idx >> 7) & 1;
        int kt = (idx >> 8) & 7, mt = (idx >> 11) & 1, w = (idx >> 12) & 7;
        int cta = idx >> 15;
        int r = mt * 16 + (lane >> 2) + (reg & 1) * 8;
        int k = w * 128 + kt * 16 + (lane & 3) * 2 + (reg >> 1) * 8;
        int g = r >> 3, jj = r & 7, j = cta * 8 + jj;
        const float* W = (g == 0) ? wf : (g == 1) ? wi : (g == 2) ? wo : wc;
        g_Wfrag[idx] = split_word(W[(size_t)j * H_ + k], W[(size_t)j * H_ + k + 1], split);
    }
}
__global__ void prep_wxfrag(const float* __restrict__ wf, const float* __restrict__ wi,
                            const float* __restrict__ wo, const float* __restrict__ wc) {
    const int total = 128 << 13;
    for (int idx = blockIdx.x * blockDim.x + threadIdx.x; idx < total;
         idx += gridDim.x * blockDim.x) {
        int lane = idx & 31, reg = (idx >> 5) & 3, split = (idx >> 7) & 1;
        int kt = (idx >> 8) & 1, mt = (idx >> 9) & 1, w = (idx >> 10) & 7;
        int cta = idx >> 13;
        int r = mt * 16 + (lane >> 2) + (reg & 1) * 8;
        int k = w * 32 + kt * 16 + (lane & 3) * 2 + (reg >> 1) * 8;
        int g = r >> 3, jj = r & 7, j = cta * 8 + jj;
        const float* W = (g == 0) ? wf : (g == 1) ? wi : (g == 2) ? wo : wc;
        g_WXfrag[idx] = split_word(W[(size_t)j * F_ + k], W[(size_t)j * F_ + k + 1], split);
    }
}
__global__ void prep_xfrag(const float* __restrict__ x) {
    const int total = T_ << 14;  // 16384 u32 per timestep
    for (int idx = blockIdx.x * blockDim.x + threadIdx.x; idx < total;
         idx += gridDim.x * blockDim.x) {
        int rb = idx & 1, lane = (idx >> 1) & 31, split = (idx >> 6) & 1;
        int nt = (idx >> 7) & 7, kt = (idx >> 10) & 1, w = (idx >> 11) & 7;
        int t = idx >> 14;
        int b = nt * 8 + (lane >> 2);
        int f = w * 32 + kt * 16 + rb * 8 + (lane & 3) * 2;
        const float* xp = x + ((size_t)t * B_ + b) * F_ + f;
        g_xfrag[idx] = split_word(xp[0], xp[1], split);
    }
}
__global__ void prep_fc(const float* __restrict__ fco_w) {
    const int total = 9 * H_ * 32;
    for (int idx = blockIdx.x * blockDim.x + threadIdx.x; idx < total;
         idx += gridDim.x * blockDim.x) {
        int cc = idx & 31, k = (idx >> 5) & (H_ - 1), ct = idx >> 15;
        int c = ct * 32 + cc;
        g_FCpk[idx] = (c < C_) ? fco_w[(size_t)c * H_ + k] : 0.0f;
    }
}
__global__ void prep_zero() {
    int i = blockIdx.x * blockDim.x + threadIdx.x;
    if (i < T_ * 128) g_flag[i] = 0;
}

// ---------------- SIMT GEMM core (kept for k_out) ----------------
template <int NK>
__device__ __forceinline__ void gemm_core(const float4* __restrict__ Ag,
                                          const float4* __restrict__ Bg,
                                          float4 (*sA)[256], float4 (*sB)[512],
                                          ull (&acc)[4][2]) {
    const int tid = threadIdx.x, tn = tid >> 4, tb = tid & 15;
    float4 ra0, ra1, rb0, rb1, rb2, rb3;
    ra0 = Ag[tid]; ra1 = Ag[tid + 128];
    rb0 = Bg[tid]; rb1 = Bg[tid + 128]; rb2 = Bg[tid + 256]; rb3 = Bg[tid + 384];
    sA[0][tid] = ra0; sA[0][tid + 128] = ra1;
    sB[0][tid] = rb0; sB[0][tid + 128] = rb1;
    sB[0][tid + 256] = rb2; sB[0][tid + 384] = rb3;
    __syncthreads();
#pragma unroll 1
    for (int ch = 0; ch < NK; ++ch) {
        const int cur = ch & 1, nxt = cur ^ 1;
        if (ch + 1 < NK) {
            const float4* An = Ag + (size_t)(ch + 1) * 256;
            const float4* Bn = Bg + (size_t)(ch + 1) * 512;
            ra0 = An[tid]; ra1 = An[tid + 128];
            rb0 = Bn[tid]; rb1 = Bn[tid + 128];
            rb2 = Bn[tid + 256]; rb3 = Bn[tid + 384];
        }
        const float4* A = sA[cur];
        const float4* Bv = sB[cur];
#pragma unroll
        for (int kk = 0; kk < 32; ++kk) {
            float4 a = A[kk * 8 + tn];
            const ull* bp = reinterpret_cast<const ull*>(&Bv[kk * 16 + tb]);
            ull b0 = bp[0], b1 = bp[1];
            ull a0 = pkdup(a.x), a1 = pkdup(a.y), a2 = pkdup(a.z), a3 = pkdup(a.w);
            fma2(acc[0][0], a0, b0); fma2(acc[0][1], a0, b1);
            fma2(acc[1][0], a1, b0); fma2(acc[1][1], a1, b1);
            fma2(acc[2][0], a2, b0); fma2(acc[2][1], a2, b1);
            fma2(acc[3][0], a3, b0); fma2(acc[3][1], a3, b1);
        }
        __syncthreads();
        if (ch + 1 < NK) {
            sA[nxt][tid] = ra0; sA[nxt][tid + 128] = ra1;
            sB[nxt][tid] = rb0; sB[nxt][tid + 128] = rb1;
            sB[nxt][tid + 256] = rb2; sB[nxt][tid + 384] = rb3;
            __syncthreads();
        }
    }
}

// ---------------- gates GEMM via mma.sync ----------------
// grid (128 jt, 8 ts); CTA loops 64 timesteps with A frags in registers.
#define SM_PART 0
#define SM_ZBUF 65536
#define REC_SMEM (65536 + 32 * 66 * 4)

__global__ void __launch_bounds__(256, 1) k_gates_mma(
    const float* __restrict__ bfp, const float* __restrict__ bip,
    const float* __restrict__ bop, const float* __restrict__ bcp) {
    extern __shared__ unsigned char sm[];
    float* part = reinterpret_cast<float*>(sm + SM_PART);
    float* zbuf = reinterpret_cast<float*>(sm + SM_ZBUF);
    const int tid = threadIdx.x, w = tid >> 5, lane = tid & 31;
    const int jt = blockIdx.x, ts = blockIdx.y;

    uint32_t A[2][2][2][4];
    {
        const uint32_t* src = g_WXfrag + ((size_t)jt * 8 + w) * 1024 + lane;
#pragma unroll
        for (int mt = 0; mt < 2; ++mt)
#pragma unroll
            for (int kt = 0; kt < 2; ++kt)
#pragma unroll
                for (int sp = 0; sp < 2; ++sp)
#pragma unroll
                    for (int rg = 0; rg < 4; ++rg)
                        A[mt][kt][sp][rg] =
                            src[((((mt * 2 + kt) * 2 + sp) * 4 + rg) << 5)];
    }
    const int jj = tid >> 5, b0 = (tid & 31) * 2, j = jt * 8 + jj;
    const float bfv = bfp[j], biv = bip[j], bov = bop[j], bcv = bcp[j];

#pragma unroll 1
    for (int tt = 0; tt < 64; ++tt) {
        const int t = ts * 64 + tt;
        const uint32_t* ximg = g_xfrag + ((size_t)t << 14);
        float D[2][8][4];
#pragma unroll
        for (int mt = 0; mt < 2; ++mt)
#pragma unroll
            for (int nt = 0; nt < 8; ++nt)
#pragma unroll
                for (int rg = 0; rg < 4; ++rg) D[mt][nt][rg] = 0.f;
#pragma unroll
        for (int kt = 0; kt < 2; ++kt) {
#pragma unroll
            for (int nt = 0; nt < 8; ++nt) {
                const uint32_t* bb =
                    ximg + (((w * 2 + kt) * 8 + nt) * 2) * 64 + lane * 2;
                uint2 bh = *reinterpret_cast<const uint2*>(bb);
                uint2 bl = *reinterpret_cast<const uint2*>(bb + 64);
#pragma unroll
                for (int mt = 0; mt < 2; ++mt) {
                    mma_bf16(D[mt][nt][0], D[mt][nt][1], D[mt][nt][2], D[mt][nt][3],
                             A[mt][kt][0][0], A[mt][kt][0][1], A[mt][kt][0][2],
                             A[mt][kt][0][3], bh.x, bh.y);
                    mma_bf16(D[mt][nt][0], D[mt][nt][1], D[mt][nt][2], D[mt][nt][3],
                             A[mt][kt][0][0], A[mt][kt][0][1], A[mt][kt][0][2],
                             A[mt][kt][0][3], bl.x, bl.y);
                    mma_bf16(D[mt][nt][0], D[mt][nt][1], D[mt][nt][2], D[mt][nt][3],
                             A[mt][kt][1][0], A[mt][kt][1][1], A[mt][kt][1][2],
                             A[mt][kt][1][3], bh.x, bh.y);
                }
            }
        }
#pragma unroll
        for (int mt = 0; mt < 2; ++mt)
#pragma unroll
            for (int nt = 0; nt < 8; ++nt)
                *reinterpret_cast<float4*>(
                    part + ((((w * 2 + mt) * 8 + nt) * 32) + lane) * 4) =
                    make_float4(D[mt][nt][0], D[mt][nt][1], D[mt][nt][2], D[mt][nt][3]);
        __syncthreads();
#pragma unroll
        for (int cc = 0; cc < 2; ++cc) {
            int c = tid + cc * 256;
            int mt = c >> 8, nt = (c >> 5) & 7, ln = c & 31;
            float4 s = make_float4(0.f, 0.f, 0.f, 0.f);
#pragma unroll
            for (int ww = 0; ww < 8; ++ww) {
                float4 p = *reinterpret_cast<const float4*>(
                    part + ((((ww * 2 + mt) * 8 + nt) * 32) + ln) * 4);
                s.x += p.x; s.y += p.y; s.z += p.z; s.w += p.w;
            }
            int r = mt * 16 + (ln >> 2);
            int n = nt * 8 + (ln & 3) * 2;
            *reinterpret_cast<float2*>(zbuf + r * 66 + n) = make_float2(s.x, s.y);
            *reinterpret_cast<float2*>(zbuf + (r + 8) * 66 + n) = make_float2(s.z, s.w);
        }
        __syncthreads();
        float za[4][2];
#pragma unroll
        for (int g = 0; g < 4; ++g) {
            float2 v = *reinterpret_cast<const float2*>(zbuf + (g * 8 + jj) * 66 + b0);
            za[g][0] = v.x; za[g][1] = v.y;
        }
        float4* G = reinterpret_cast<float4*>(g_gates) + ((size_t)t * H_ + j) * 64 + b0;
        G[0] = make_float4(za[0][0] + bfv, za[1][0] + biv, za[2][0] + bov, za[3][0] + bcv);
        G[1] = make_float4(za[0][1] + bfv, za[1][1] + biv, za[2][1] + bov, za[3][1] + bcv);
        __syncthreads();
    }
}

// ---------------- persistent mma.sync recurrence ----------------
// 128 CTAs x 256 thr. Warp w owns K-slice w*128..+127 (producers: CTAs
// w*16..+15) -> per-warp fine-grained acquire waits; no CTA-wide pre-wait.
__global__ void __launch_bounds__(256, 1) k_rec3() {
    extern __shared__ unsigned char sm[];
    float* part = reinterpret_cast<float*>(sm + SM_PART);
    float* zbuf = reinterpret_cast<float*>(sm + SM_ZBUF);

    const int tid = threadIdx.x, w = tid >> 5, lane = tid & 31;
    const int cta = blockIdx.x;

    uint32_t A[2][8][2][4];
    {
        const uint32_t* src = g_Wfrag + ((size_t)cta * 8 + w) * 4096 + lane;
#pragma unroll
        for (int mt = 0; mt < 2; ++mt)
#pragma unroll
            for (int kt = 0; kt < 8; ++kt)
#pragma unroll
                for (int sp = 0; sp < 2; ++sp)
#pragma unroll
                    for (int rg = 0; rg < 4; ++rg)
                        A[mt][kt][sp][rg] =
                            src[((((mt * 8 + kt) * 2 + sp) * 4 + rg) << 5)];
    }

    const int jj = tid >> 5, b0 = (tid & 31) * 2, j = cta * 8 + jj;
    float cst0 = 0.f, cst1 = 0.f;
    const int w_j = j >> 7, kt_j = (j >> 4) & 7, rb_j = (j >> 3) & 1;
    const int byte_in = (j & 1) * 2;
    const int l_j0 = ((b0 & 7) << 2) + ((j & 7) >> 1);
    const int l_j1 = (((b0 + 1) & 7) << 2) + ((j & 7) >> 1);

#pragma unroll 1
    for (int t = 0; t < T_; ++t) {
        const float4* G4 = reinterpret_cast<const float4*>(g_gates) +
                           ((size_t)t * H_ + j) * 64 + b0;
        float4 gx0 = G4[0], gx1 = G4[1];

        float zadd[4][2];
        if (t > 0) {
            // Per-warp wait: only this warp's 16 producers.
            {
                const int* f = g_flag + (t - 1) * 128 + w * 16 + (lane & 15);
                int v;
                do {
                    asm volatile("ld.acquire.gpu.global.b32 %0, [%1];"
                                 : "=r"(v) : "l"(f));
                } while (!v);
                __syncwarp();
            }

            float D[2][8][4];
#pragma unroll
            for (int mt = 0; mt < 2; ++mt)
#pragma unroll
                for (int nt = 0; nt < 8; ++nt)
#pragma unroll
                    for (int rg = 0; rg < 4; ++rg) D[mt][nt][rg] = 0.f;

            const uint32_t* himg = g_hfrag + (size_t)((t - 1) & 1) * 65536;
#pragma unroll
            for (int kt = 0; kt < 8; ++kt) {
#pragma unroll
                for (int nt = 0; nt < 8; ++nt) {
                    const uint32_t* bb =
                        himg + (((w * 8 + kt) * 8 + nt) * 2) * 64 + lane * 2;
                    uint2 bh = ldg_cg2(bb);
                    uint2 bl = ldg_cg2(bb + 64);
#pragma unroll
                    for (int mt = 0; mt < 2; ++mt) {
                        mma_bf16(D[mt][nt][0], D[mt][nt][1], D[mt][nt][2], D[mt][nt][3],
                                 A[mt][kt][0][0], A[mt][kt][0][1], A[mt][kt][0][2],
                                 A[mt][kt][0][3], bh.x, bh.y);
                        mma_bf16(D[mt][nt][0], D[mt][nt][1], D[mt][nt][2], D[mt][nt][3],
                                 A[mt][kt][0][0], A[mt][kt][0][1], A[mt][kt][0][2],
                                 A[mt][kt][0][3], bl.x, bl.y);
                        mma_bf16(D[mt][nt][0], D[mt][nt][1], D[mt][nt][2], D[mt][nt][3],
                                 A[mt][kt][1][0], A[mt][kt][1][1], A[mt][kt][1][2],
                                 A[mt][kt][1][3], bh.x, bh.y);
                    }
                }
            }
#pragma unroll
            for (int mt = 0; mt < 2; ++mt)
#pragma unroll
                for (int nt = 0; nt < 8; ++nt)
                    *reinterpret_cast<float4*>(
                        part + ((((w * 2 + mt) * 8 + nt) * 32) + lane) * 4) =
                        make_float4(D[mt][nt][0], D[mt][nt][1], D[mt][nt][2],
                                    D[mt][nt][3]);
            __syncthreads();
#pragma unroll
            for (int cc = 0; cc < 2; ++cc) {
                int c = tid + cc * 256;
                int mt = c >> 8, nt = (c >> 5) & 7, ln = c & 31;
                float4 s = make_float4(0.f, 0.f, 0.f, 0.f);
#pragma unroll
                for (int ww = 0; ww < 8; ++ww) {
                    float4 p = *reinterpret_cast<const float4*>(
                        part + ((((ww * 2 + mt) * 8 + nt) * 32) + ln) * 4);
                    s.x += p.x; s.y += p.y; s.z += p.z; s.w += p.w;
                }
                int r = mt * 16 + (ln >> 2);
                int n = nt * 8 + (ln & 3) * 2;
                *reinterpret_cast<float2*>(zbuf + r * 66 + n) = make_float2(s.x, s.y);
                *reinterpret_cast<float2*>(zbuf + (r + 8) * 66 + n) =
                    make_float2(s.z, s.w);
            }
            __syncthreads();
#pragma unroll
            for (int g = 0; g < 4; ++g) {
                float2 v = *reinterpret_cast<const float2*>(zbuf + (g * 8 + jj) * 66 + b0);
                zadd[g][0] = v.x;
                zadd[g][1] = v.y;
            }
        } else {
#pragma unroll
            for (int g = 0; g < 4; ++g) zadd[g][0] = zadd[g][1] = 0.f;
        }

        float ft0 = sigf(gx0.x + zadd[0][0]), it0 = sigf(gx0.y + zadd[1][0]);
        float ot0 = sigf(gx0.z + zadd[2][0]);
        cst0 = it0 * tanh_acc(gx0.w + zadd[3][0]) + ft0 * cst0;
        float h0 = ot0 * tanh_acc(cst0);
        float ft1 = sigf(gx1.x + zadd[0][1]), it1 = sigf(gx1.y + zadd[1][1]);
        float ot1 = sigf(gx1.z + zadd[2][1]);
        cst1 = it1 * tanh_acc(gx1.w + zadd[3][1]) + ft1 * cst1;
        float h1 = ot1 * tanh_acc(cst1);

        *reinterpret_cast<float2*>(g_hT + ((size_t)t * H_ + j) * B_ + b0) =
            make_float2(h0, h1);
        {
            uint32_t* img = g_hfrag + (size_t)(t & 1) * 65536;
            const int nt = b0 >> 3;
            size_t base = (((w_j * 8 + kt_j) * 8 + nt) * 2) * 64;
            unsigned char* pH0 = (unsigned char*)(img + base + l_j0 * 2 + rb_j) + byte_in;
            unsigned char* pH1 = (unsigned char*)(img + base + l_j1 * 2 + rb_j) + byte_in;
            unsigned char* pL0 = pH0 + 64 * 4;
            unsigned char* pL1 = pH1 + 64 * 4;
            __nv_bfloat16 h0h = __float2bfloat16(h0);
            __nv_bfloat16 h1h = __float2bfloat16(h1);
            *(__nv_bfloat16*)pH0 = h0h;
            *(__nv_bfloat16*)pH1 = h1h;
            *(__nv_bfloat16*)pL0 = __float2bfloat16(h0 - __bfloat162float(h0h));
            *(__nv_bfloat16*)pL1 = __float2bfloat16(h1 - __bfloat162float(h1h));
        }
        __syncthreads();
        if (tid == 0) {
            asm volatile("st.release.gpu.global.b32 [%0], %1;"
                         :: "l"(g_flag + t * 128 + cta), "r"(1) : "memory");
        }
    }
}

// ---------------- output projection (SIMT, kept) ----------------
__global__ void k_out(const float* __restrict__ fco_b, float* __restrict__ out) {
    const int ct = blockIdx.x, t = blockIdx.y;
    __shared__ float4 sA[2][256];
    __shared__ float4 sB[2][512];
    ull acc[4][2] = {};
    const float4* Ag = reinterpret_cast<const float4*>(g_FCpk) + (size_t)ct * H_ * 8;
    const float4* Bg = reinterpret_cast<const float4*>(g_hT) + (size_t)t * H_ * 16;
    gemm_core<H_ / 32>(Ag, Bg, sA, sB, acc);
    const int tn = threadIdx.x >> 4, tb = threadIdx.x & 15, c0 = ct * 32 + tn * 4;
    float z[4][4];
#pragma unroll
    for (int r = 0; r < 4; ++r) {
        z[r][0] = lo2(acc[r][0]); z[r][1] = hi2(acc[r][0]);
        z[r][2] = lo2(acc[r][1]); z[r][3] = hi2(acc[r][1]);
    }
#pragma unroll
    for (int bb = 0; bb < 4; ++bb) {
        const int b = tb * 4 + bb;
        float* o = out + ((size_t)t * B_ + b) * C_;
#pragma unroll
        for (int ci = 0; ci < 4; ++ci) {
            const int c = c0 + ci;
            if (c < C_) o[c] = z[ci][bb] + fco_b[c];
        }
    }
}

// ---------------- launch ----------------
extern "C" void kernel_launch(void* const* d_in, const int* in_sizes, int n_in,
                              void* d_out, int out_size) {
    const float* x     = (const float*)d_in[0];
    const float* wfx_w = (const float*)d_in[1];
    const float* wfx_b = (const float*)d_in[2];
    const float* wix_w = (const float*)d_in[3];
    const float* wix_b = (const float*)d_in[4];
    const float* wox_w = (const float*)d_in[5];
    const float* wox_b = (const float*)d_in[6];
    const float* wcx_w = (const float*)d_in[7];
    const float* wcx_b = (const float*)d_in[8];
    const float* wfh_w = (const float*)d_in[9];
    const float* wih_w = (const float*)d_in[10];
    const float* woh_w = (const float*)d_in[11];
    const float* wch_w = (const float*)d_in[12];
    const float* fco_w = (const float*)d_in[13];
    const float* fco_b = (const float*)d_in[14];
    float* out = (float*)d_out;
    (void)in_sizes; (void)n_in; (void)out_size;

    cudaFuncSetAttribute(k_rec3, cudaFuncAttributeMaxDynamicSharedMemorySize,
                         REC_SMEM);
    cudaFuncSetAttribute(k_gates_mma, cudaFuncAttributeMaxDynamicSharedMemorySize,
                         REC_SMEM);

    prep_wfrag<<<8192, 256>>>(wfh_w, wih_w, woh_w, wch_w);
    prep_wxfrag<<<2048, 256>>>(wfx_w, wix_w, wox_w, wcx_w);
    prep_xfrag<<<8192, 256>>>(x);
    prep_fc<<<576, 256>>>(fco_w);
    prep_zero<<<256, 256>>>();

    k_gates_mma<<<dim3(128, 8), 256, REC_SMEM>>>(wfx_b, wix_b, wox_b, wcx_b);

    k_rec3<<<128, 256, REC_SMEM>>>();

    k_out<<<dim3(9, 512), 128>>>(fco_b, out);
}

// round 15
// speedup vs baseline: 1.3307x; 1.1033x over previous
#include <cuda_runtime.h>
#include <cuda_fp16.h>
#include <math.h>
#include <stdint.h>

typedef unsigned long long ull;

#define T_ 512
#define B_ 64
#define F_ 256
#define H_ 1024
#define C_ 257

// ---------------- scratch ----------------
__device__ float g_gates[(size_t)T_ * H_ * B_ * 4]; // [t][j][b][g]
__device__ float g_hT[(size_t)T_ * H_ * B_];        // [t][j][b] (k_out)
__device__ float g_FCpk[(size_t)9 * H_ * 32];
// W (recurrent) fp16 A-frag order: [cta][w8][mt2][kt8][split2][reg4][lane32]
__device__ uint32_t g_Wfrag[(size_t)128 * 8 * 2 * 8 * 2 * 4 * 32];
// Wx (input) fp16 A-frag order: [cta][w8][mt2][kt2][split2][reg4][lane32]
__device__ uint32_t g_WXfrag[(size_t)128 * 8 * 2 * 2 * 2 * 4 * 32];
// h fp16 (single) B-frag order: [parity2][w8][kt8][nt8][lane32][rb2]
__device__ uint32_t g_hfrag[(size_t)2 * 32768];
// x fp16 (single) B-frag order: [t][w8][kt2][nt8][lane32][rb2] = 8192 u32/t
__device__ uint32_t g_xfrag[(size_t)T_ * 8192];
__device__ int g_flag[(size_t)T_ * 128];

// ---------------- helpers ----------------
__device__ __forceinline__ ull pkdup(float v) {
    ull r; asm("mov.b64 %0, {%1, %1};" : "=l"(r) : "r"(__float_as_uint(v))); return r;
}
__device__ __forceinline__ void fma2(ull& d, ull a, ull b) {
    asm("fma.rn.f32x2 %0, %1, %2, %0;" : "+l"(d) : "l"(a), "l"(b));
}
__device__ __forceinline__ float lo2(ull v) { return __uint_as_float((unsigned)v); }
__device__ __forceinline__ float hi2(ull v) { return __uint_as_float((unsigned)(v >> 32)); }
__device__ __forceinline__ float sigf(float x) { return 1.0f / (1.0f + expf(-x)); }
__device__ __forceinline__ float tanh_acc(float x) {
    float ax = fabsf(x), e = expf(-2.0f * ax);
    return copysignf((1.0f - e) / (1.0f + e), x);
}
__device__ __forceinline__ uint2 ldg_cg2(const uint32_t* p) {
    uint2 v;
    asm volatile("ld.global.cg.v2.u32 {%0,%1}, [%2];" : "=r"(v.x), "=r"(v.y) : "l"(p));
    return v;
}
__device__ __forceinline__ void mma_f16(float& d0, float& d1, float& d2, float& d3,
                                        uint32_t a0, uint32_t a1, uint32_t a2,
                                        uint32_t a3, uint32_t b0, uint32_t b1) {
    asm volatile(
        "mma.sync.aligned.m16n8k16.row.col.f32.f16.f16.f32 "
        "{%0,%1,%2,%3},{%4,%5,%6,%7},{%8,%9},{%0,%1,%2,%3};"
        : "+f"(d0), "+f"(d1), "+f"(d2), "+f"(d3)
        : "r"(a0), "r"(a1), "r"(a2), "r"(a3), "r"(b0), "r"(b1));
}
__device__ __forceinline__ uint32_t h16bits(float v) {
    return (uint32_t)__half_as_ushort(__float2half(v));
}
// fp16 pack: split 0 = hi halves, split 1 = residual halves
__device__ __forceinline__ uint32_t split_word16(float v0, float v1, int split) {
    if (split == 0) return h16bits(v0) | (h16bits(v1) << 16);
    float h0 = __half2float(__float2half(v0));
    float h1 = __half2float(__float2half(v1));
    return h16bits(v0 - h0) | (h16bits(v1 - h1) << 16);
}
__device__ __forceinline__ uint32_t pack16(float v0, float v1) {
    return h16bits(v0) | (h16bits(v1) << 16);
}

// ---------------- prep kernels ----------------
__global__ void prep_wfrag(const float* __restrict__ wf, const float* __restrict__ wi,
                           const float* __restrict__ wo, const float* __restrict__ wc) {
    const int total = 128 << 15;
    for (int idx = blockIdx.x * blockDim.x + threadIdx.x; idx < total;
         idx += gridDim.x * blockDim.x) {
        int lane = idx & 31, reg = (idx >> 5) & 3, split = (idx >> 7) & 1;
        int kt = (idx >> 8) & 7, mt = (idx >> 11) & 1, w = (idx >> 12) & 7;
        int cta = idx >> 15;
        int r = mt * 16 + (lane >> 2) + (reg & 1) * 8;
        int k = w * 128 + kt * 16 + (lane & 3) * 2 + (reg >> 1) * 8;
        int g = r >> 3, jj = r & 7, j = cta * 8 + jj;
        const float* W = (g == 0) ? wf : (g == 1) ? wi : (g == 2) ? wo : wc;
        g_Wfrag[idx] =
            split_word16(W[(size_t)j * H_ + k], W[(size_t)j * H_ + k + 1], split);
    }
}
__global__ void prep_wxfrag(const float* __restrict__ wf, const float* __restrict__ wi,
                            const float* __restrict__ wo, const float* __restrict__ wc) {
    const int total = 128 << 13;
    for (int idx = blockIdx.x * blockDim.x + threadIdx.x; idx < total;
         idx += gridDim.x * blockDim.x) {
        int lane = idx & 31, reg = (idx >> 5) & 3, split = (idx >> 7) & 1;
        int kt = (idx >> 8) & 1, mt = (idx >> 9) & 1, w = (idx >> 10) & 7;
        int cta = idx >> 13;
        int r = mt * 16 + (lane >> 2) + (reg & 1) * 8;
        int k = w * 32 + kt * 16 + (lane & 3) * 2 + (reg >> 1) * 8;
        int g = r >> 3, jj = r & 7, j = cta * 8 + jj;
        const float* W = (g == 0) ? wf : (g == 1) ? wi : (g == 2) ? wo : wc;
        g_WXfrag[idx] =
            split_word16(W[(size_t)j * F_ + k], W[(size_t)j * F_ + k + 1], split);
    }
}
__global__ void prep_xfrag(const float* __restrict__ x) {
    const int total = T_ << 13;  // 8192 u32 per timestep (single split)
    for (int idx = blockIdx.x * blockDim.x + threadIdx.x; idx < total;
         idx += gridDim.x * blockDim.x) {
        int rb = idx & 1, lane = (idx >> 1) & 31;
        int nt = (idx >> 6) & 7, kt = (idx >> 9) & 1, w = (idx >> 10) & 7;
        int t = idx >> 13;
        int b = nt * 8 + (lane >> 2);
        int f = w * 32 + kt * 16 + rb * 8 + (lane & 3) * 2;
        const float* xp = x + ((size_t)t * B_ + b) * F_ + f;
        g_xfrag[idx] = pack16(xp[0], xp[1]);
    }
}
__global__ void prep_fc(const float* __restrict__ fco_w) {
    const int total = 9 * H_ * 32;
    for (int idx = blockIdx.x * blockDim.x + threadIdx.x; idx < total;
         idx += gridDim.x * blockDim.x) {
        int cc = idx & 31, k = (idx >> 5) & (H_ - 1), ct = idx >> 15;
        int c = ct * 32 + cc;
        g_FCpk[idx] = (c < C_) ? fco_w[(size_t)c * H_ + k] : 0.0f;
    }
}
__global__ void prep_zero() {
    int i = blockIdx.x * blockDim.x + threadIdx.x;
    if (i < T_ * 128) g_flag[i] = 0;
}

// ---------------- SIMT GEMM core (kept for k_out) ----------------
template <int NK>
__device__ __forceinline__ void gemm_core(const float4* __restrict__ Ag,
                                          const float4* __restrict__ Bg,
                                          float4 (*sA)[256], float4 (*sB)[512],
                                          ull (&acc)[4][2]) {
    const int tid = threadIdx.x, tn = tid >> 4, tb = tid & 15;
    float4 ra0, ra1, rb0, rb1, rb2, rb3;
    ra0 = Ag[tid]; ra1 = Ag[tid + 128];
    rb0 = Bg[tid]; rb1 = Bg[tid + 128]; rb2 = Bg[tid + 256]; rb3 = Bg[tid + 384];
    sA[0][tid] = ra0; sA[0][tid + 128] = ra1;
    sB[0][tid] = rb0; sB[0][tid + 128] = rb1;
    sB[0][tid + 256] = rb2; sB[0][tid + 384] = rb3;
    __syncthreads();
#pragma unroll 1
    for (int ch = 0; ch < NK; ++ch) {
        const int cur = ch & 1, nxt = cur ^ 1;
        if (ch + 1 < NK) {
            const float4* An = Ag + (size_t)(ch + 1) * 256;
            const float4* Bn = Bg + (size_t)(ch + 1) * 512;
            ra0 = An[tid]; ra1 = An[tid + 128];
            rb0 = Bn[tid]; rb1 = Bn[tid + 128];
            rb2 = Bn[tid + 256]; rb3 = Bn[tid + 384];
        }
        const float4* A = sA[cur];
        const float4* Bv = sB[cur];
#pragma unroll
        for (int kk = 0; kk < 32; ++kk) {
            float4 a = A[kk * 8 + tn];
            const ull* bp = reinterpret_cast<const ull*>(&Bv[kk * 16 + tb]);
            ull b0 = bp[0], b1 = bp[1];
            ull a0 = pkdup(a.x), a1 = pkdup(a.y), a2 = pkdup(a.z), a3 = pkdup(a.w);
            fma2(acc[0][0], a0, b0); fma2(acc[0][1], a0, b1);
            fma2(acc[1][0], a1, b0); fma2(acc[1][1], a1, b1);
            fma2(acc[2][0], a2, b0); fma2(acc[2][1], a2, b1);
            fma2(acc[3][0], a3, b0); fma2(acc[3][1], a3, b1);
        }
        __syncthreads();
        if (ch + 1 < NK) {
            sA[nxt][tid] = ra0; sA[nxt][tid + 128] = ra1;
            sB[nxt][tid] = rb0; sB[nxt][tid + 128] = rb1;
            sB[nxt][tid + 256] = rb2; sB[nxt][tid + 384] = rb3;
            __syncthreads();
        }
    }
}

// ---------------- gates GEMM via mma.sync (fp16, 2 products) ----------------
#define SM_PART 0
#define SM_ZBUF 65536
#define REC_SMEM (65536 + 32 * 66 * 4)

__global__ void __launch_bounds__(256, 1) k_gates_mma(
    const float* __restrict__ bfp, const float* __restrict__ bip,
    const float* __restrict__ bop, const float* __restrict__ bcp) {
    extern __shared__ unsigned char sm[];
    float* part = reinterpret_cast<float*>(sm + SM_PART);
    float* zbuf = reinterpret_cast<float*>(sm + SM_ZBUF);
    const int tid = threadIdx.x, w = tid >> 5, lane = tid & 31;
    const int jt = blockIdx.x, ts = blockIdx.y;

    uint32_t A[2][2][2][4];
    {
        const uint32_t* src = g_WXfrag + ((size_t)jt * 8 + w) * 1024 + lane;
#pragma unroll
        for (int mt = 0; mt < 2; ++mt)
#pragma unroll
            for (int kt = 0; kt < 2; ++kt)
#pragma unroll
                for (int sp = 0; sp < 2; ++sp)
#pragma unroll
                    for (int rg = 0; rg < 4; ++rg)
                        A[mt][kt][sp][rg] =
                            src[((((mt * 2 + kt) * 2 + sp) * 4 + rg) << 5)];
    }
    const int jj = tid >> 5, b0 = (tid & 31) * 2, j = jt * 8 + jj;
    const float bfv = bfp[j], biv = bip[j], bov = bop[j], bcv = bcp[j];

#pragma unroll 1
    for (int tt = 0; tt < 64; ++tt) {
        const int t = ts * 64 + tt;
        const uint32_t* ximg = g_xfrag + ((size_t)t << 13);
        float D[2][8][4];
#pragma unroll
        for (int mt = 0; mt < 2; ++mt)
#pragma unroll
            for (int nt = 0; nt < 8; ++nt)
#pragma unroll
                for (int rg = 0; rg < 4; ++rg) D[mt][nt][rg] = 0.f;
#pragma unroll
        for (int kt = 0; kt < 2; ++kt) {
#pragma unroll
            for (int nt = 0; nt < 8; ++nt) {
                const uint32_t* bb = ximg + ((w * 2 + kt) * 8 + nt) * 64 + lane * 2;
                uint2 bh = *reinterpret_cast<const uint2*>(bb);
#pragma unroll
                for (int mt = 0; mt < 2; ++mt) {
                    mma_f16(D[mt][nt][0], D[mt][nt][1], D[mt][nt][2], D[mt][nt][3],
                            A[mt][kt][0][0], A[mt][kt][0][1], A[mt][kt][0][2],
                            A[mt][kt][0][3], bh.x, bh.y);
                    mma_f16(D[mt][nt][0], D[mt][nt][1], D[mt][nt][2], D[mt][nt][3],
                            A[mt][kt][1][0], A[mt][kt][1][1], A[mt][kt][1][2],
                            A[mt][kt][1][3], bh.x, bh.y);
                }
            }
        }
#pragma unroll
        for (int mt = 0; mt < 2; ++mt)
#pragma unroll
            for (int nt = 0; nt < 8; ++nt)
                *reinterpret_cast<float4*>(
                    part + ((((w * 2 + mt) * 8 + nt) * 32) + lane) * 4) =
                    make_float4(D[mt][nt][0], D[mt][nt][1], D[mt][nt][2], D[mt][nt][3]);
        __syncthreads();
#pragma unroll
        for (int cc = 0; cc < 2; ++cc) {
            int c = tid + cc * 256;
            int mt = c >> 8, nt = (c >> 5) & 7, ln = c & 31;
            float4 s = make_float4(0.f, 0.f, 0.f, 0.f);
#pragma unroll
            for (int ww = 0; ww < 8; ++ww) {
                float4 p = *reinterpret_cast<const float4*>(
                    part + ((((ww * 2 + mt) * 8 + nt) * 32) + ln) * 4);
                s.x += p.x; s.y += p.y; s.z += p.z; s.w += p.w;
            }
            int r = mt * 16 + (ln >> 2);
            int n = nt * 8 + (ln & 3) * 2;
            *reinterpret_cast<float2*>(zbuf + r * 66 + n) = make_float2(s.x, s.y);
            *reinterpret_cast<float2*>(zbuf + (r + 8) * 66 + n) = make_float2(s.z, s.w);
        }
        __syncthreads();
        float za[4][2];
#pragma unroll
        for (int g = 0; g < 4; ++g) {
            float2 v = *reinterpret_cast<const float2*>(zbuf + (g * 8 + jj) * 66 + b0);
            za[g][0] = v.x; za[g][1] = v.y;
        }
        float4* G = reinterpret_cast<float4*>(g_gates) + ((size_t)t * H_ + j) * 64 + b0;
        G[0] = make_float4(za[0][0] + bfv, za[1][0] + biv, za[2][0] + bov, za[3][0] + bcv);
        G[1] = make_float4(za[0][1] + bfv, za[1][1] + biv, za[2][1] + bov, za[3][1] + bcv);
        __syncthreads();
    }
}

// ---------------- persistent mma.sync recurrence (fp16, 2 products) --------
__global__ void __launch_bounds__(256, 1) k_rec3() {
    extern __shared__ unsigned char sm[];
    float* part = reinterpret_cast<float*>(sm + SM_PART);
    float* zbuf = reinterpret_cast<float*>(sm + SM_ZBUF);

    const int tid = threadIdx.x, w = tid >> 5, lane = tid & 31;
    const int cta = blockIdx.x;

    uint32_t A[2][8][2][4];
    {
        const uint32_t* src = g_Wfrag + ((size_t)cta * 8 + w) * 4096 + lane;
#pragma unroll
        for (int mt = 0; mt < 2; ++mt)
#pragma unroll
            for (int kt = 0; kt < 8; ++kt)
#pragma unroll
                for (int sp = 0; sp < 2; ++sp)
#pragma unroll
                    for (int rg = 0; rg < 4; ++rg)
                        A[mt][kt][sp][rg] =
                            src[((((mt * 8 + kt) * 2 + sp) * 4 + rg) << 5)];
    }

    const int jj = tid >> 5, b0 = (tid & 31) * 2, j = cta * 8 + jj;
    float cst0 = 0.f, cst1 = 0.f;
    const int w_j = j >> 7, kt_j = (j >> 4) & 7, rb_j = (j >> 3) & 1;
    const int byte_in = (j & 1) * 2;
    const int l_j0 = ((b0 & 7) << 2) + ((j & 7) >> 1);
    const int l_j1 = (((b0 + 1) & 7) << 2) + ((j & 7) >> 1);

#pragma unroll 1
    for (int t = 0; t < T_; ++t) {
        const float4* G4 = reinterpret_cast<const float4*>(g_gates) +
                           ((size_t)t * H_ + j) * 64 + b0;
        float4 gx0 = G4[0], gx1 = G4[1];

        float zadd[4][2];
        if (t > 0) {
            {
                const int* f = g_flag + (t - 1) * 128 + w * 16 + (lane & 15);
                int v;
                do {
                    asm volatile("ld.acquire.gpu.global.b32 %0, [%1];"
                                 : "=r"(v) : "l"(f));
                } while (!v);
                __syncwarp();
            }

            float D[2][8][4];
#pragma unroll
            for (int mt = 0; mt < 2; ++mt)
#pragma unroll
                for (int nt = 0; nt < 8; ++nt)
#pragma unroll
                    for (int rg = 0; rg < 4; ++rg) D[mt][nt][rg] = 0.f;

            const uint32_t* himg = g_hfrag + (size_t)((t - 1) & 1) * 32768;
#pragma unroll
            for (int kt = 0; kt < 8; ++kt) {
#pragma unroll
                for (int nt = 0; nt < 8; ++nt) {
                    const uint32_t* bb =
                        himg + ((w * 8 + kt) * 8 + nt) * 64 + lane * 2;
                    uint2 bh = ldg_cg2(bb);
#pragma unroll
                    for (int mt = 0; mt < 2; ++mt) {
                        mma_f16(D[mt][nt][0], D[mt][nt][1], D[mt][nt][2], D[mt][nt][3],
                                A[mt][kt][0][0], A[mt][kt][0][1], A[mt][kt][0][2],
                                A[mt][kt][0][3], bh.x, bh.y);
                        mma_f16(D[mt][nt][0], D[mt][nt][1], D[mt][nt][2], D[mt][nt][3],
                                A[mt][kt][1][0], A[mt][kt][1][1], A[mt][kt][1][2],
                                A[mt][kt][1][3], bh.x, bh.y);
                    }
                }
            }
#pragma unroll
            for (int mt = 0; mt < 2; ++mt)
#pragma unroll
                for (int nt = 0; nt < 8; ++nt)
                    *reinterpret_cast<float4*>(
                        part + ((((w * 2 + mt) * 8 + nt) * 32) + lane) * 4) =
                        make_float4(D[mt][nt][0], D[mt][nt][1], D[mt][nt][2],
                                    D[mt][nt][3]);
            __syncthreads();
#pragma unroll
            for (int cc = 0; cc < 2; ++cc) {
                int c = tid + cc * 256;
                int mt = c >> 8, nt = (c >> 5) & 7, ln = c & 31;
                float4 s = make_float4(0.f, 0.f, 0.f, 0.f);
#pragma unroll
                for (int ww = 0; ww < 8; ++ww) {
                    float4 p = *reinterpret_cast<const float4*>(
                        part + ((((ww * 2 + mt) * 8 + nt) * 32) + ln) * 4);
                    s.x += p.x; s.y += p.y; s.z += p.z; s.w += p.w;
                }
                int r = mt * 16 + (ln >> 2);
                int n = nt * 8 + (ln & 3) * 2;
                *reinterpret_cast<float2*>(zbuf + r * 66 + n) = make_float2(s.x, s.y);
                *reinterpret_cast<float2*>(zbuf + (r + 8) * 66 + n) =
                    make_float2(s.z, s.w);
            }
            __syncthreads();
#pragma unroll
            for (int g = 0; g < 4; ++g) {
                float2 v = *reinterpret_cast<const float2*>(zbuf + (g * 8 + jj) * 66 + b0);
                zadd[g][0] = v.x;
                zadd[g][1] = v.y;
            }
        } else {
#pragma unroll
            for (int g = 0; g < 4; ++g) zadd[g][0] = zadd[g][1] = 0.f;
        }

        float ft0 = sigf(gx0.x + zadd[0][0]), it0 = sigf(gx0.y + zadd[1][0]);
        float ot0 = sigf(gx0.z + zadd[2][0]);
        cst0 = it0 * tanh_acc(gx0.w + zadd[3][0]) + ft0 * cst0;
        float h0 = ot0 * tanh_acc(cst0);
        float ft1 = sigf(gx1.x + zadd[0][1]), it1 = sigf(gx1.y + zadd[1][1]);
        float ot1 = sigf(gx1.z + zadd[2][1]);
        cst1 = it1 * tanh_acc(gx1.w + zadd[3][1]) + ft1 * cst1;
        float h1 = ot1 * tanh_acc(cst1);

        *reinterpret_cast<float2*>(g_hT + ((size_t)t * H_ + j) * B_ + b0) =
            make_float2(h0, h1);
        {
            uint32_t* img = g_hfrag + (size_t)(t & 1) * 32768;
            const int nt = b0 >> 3;
            size_t base = ((w_j * 8 + kt_j) * 8 + nt) * 64;
            unsigned char* pH0 = (unsigned char*)(img + base + l_j0 * 2 + rb_j) + byte_in;
            unsigned char* pH1 = (unsigned char*)(img + base + l_j1 * 2 + rb_j) + byte_in;
            *(__half*)pH0 = __float2half(h0);
            *(__half*)pH1 = __float2half(h1);
        }
        __syncthreads();
        if (tid == 0) {
            asm volatile("st.release.gpu.global.b32 [%0], %1;"
                         :: "l"(g_flag + t * 128 + cta), "r"(1) : "memory");
        }
    }
}

// ---------------- output projection (SIMT, kept) ----------------
__global__ void k_out(const float* __restrict__ fco_b, float* __restrict__ out) {
    const int ct = blockIdx.x, t = blockIdx.y;
    __shared__ float4 sA[2][256];
    __shared__ float4 sB[2][512];
    ull acc[4][2] = {};
    const float4* Ag = reinterpret_cast<const float4*>(g_FCpk) + (size_t)ct * H_ * 8;
    const float4* Bg = reinterpret_cast<const float4*>(g_hT) + (size_t)t * H_ * 16;
    gemm_core<H_ / 32>(Ag, Bg, sA, sB, acc);
    const int tn = threadIdx.x >> 4, tb = threadIdx.x & 15, c0 = ct * 32 + tn * 4;
    float z[4][4];
#pragma unroll
    for (int r = 0; r < 4; ++r) {
        z[r][0] = lo2(acc[r][0]); z[r][1] = hi2(acc[r][0]);
        z[r][2] = lo2(acc[r][1]); z[r][3] = hi2(acc[r][1]);
    }
#pragma unroll
    for (int bb = 0; bb < 4; ++bb) {
        const int b = tb * 4 + bb;
        float* o = out + ((size_t)t * B_ + b) * C_;
#pragma unroll
        for (int ci = 0; ci < 4; ++ci) {
            const int c = c0 + ci;
            if (c < C_) o[c] = z[ci][bb] + fco_b[c];
        }
    }
}

// ---------------- launch ----------------
extern "C" void kernel_launch(void* const* d_in, const int* in_sizes, int n_in,
                              void* d_out, int out_size) {
    const float* x     = (const float*)d_in[0];
    const float* wfx_w = (const float*)d_in[1];
    const float* wfx_b = (const float*)d_in[2];
    const float* wix_w = (const float*)d_in[3];
    const float* wix_b = (const float*)d_in[4];
    const float* wox_w = (const float*)d_in[5];
    const float* wox_b = (const float*)d_in[6];
    const float* wcx_w = (const float*)d_in[7];
    const float* wcx_b = (const float*)d_in[8];
    const float* wfh_w = (const float*)d_in[9];
    const float* wih_w = (const float*)d_in[10];
    const float* woh_w = (const float*)d_in[11];
    const float* wch_w = (const float*)d_in[12];
    const float* fco_w = (const float*)d_in[13];
    const float* fco_b = (const float*)d_in[14];
    float* out = (float*)d_out;
    (void)in_sizes; (void)n_in; (void)out_size;

    cudaFuncSetAttribute(k_rec3, cudaFuncAttributeMaxDynamicSharedMemorySize,
                         REC_SMEM);
    cudaFuncSetAttribute(k_gates_mma, cudaFuncAttributeMaxDynamicSharedMemorySize,
                         REC_SMEM);

    prep_wfrag<<<8192, 256>>>(wfh_w, wih_w, woh_w, wch_w);
    prep_wxfrag<<<2048, 256>>>(wfx_w, wix_w, wox_w, wcx_w);
    prep_xfrag<<<4096, 256>>>(x);
    prep_fc<<<576, 256>>>(fco_w);
    prep_zero<<<256, 256>>>();

    k_gates_mma<<<dim3(128, 8), 256, REC_SMEM>>>(wfx_b, wix_b, wox_b, wcx_b);

    k_rec3<<<128, 256, REC_SMEM>>>();

    k_out<<<dim3(9, 512), 128>>>(fco_b, out);
}

// round 16
// speedup vs baseline: 1.5391x; 1.1566x over previous
#include <cuda_runtime.h>
#include <cuda_fp16.h>
#include <math.h>
#include <stdint.h>

typedef unsigned long long ull;

#define T_ 512
#define B_ 64
#define F_ 256
#define H_ 1024
#define C_ 257

// ---------------- scratch ----------------
__device__ float g_gates[(size_t)T_ * H_ * B_ * 4]; // [t][j][b][g]
__device__ float g_hT[(size_t)T_ * H_ * B_];        // [t][j][b] (k_out)
__device__ float g_FCpk[(size_t)9 * H_ * 32];
// W (recurrent) fp16 A-frag order: [cta][w8][mt2][kt8][split2][reg4][lane32]
__device__ uint32_t g_Wfrag[(size_t)128 * 8 * 2 * 8 * 2 * 4 * 32];
// Wx (input) fp16 A-frag order: [cta][w8][mt2][kt2][split2][reg4][lane32]
__device__ uint32_t g_WXfrag[(size_t)128 * 8 * 2 * 2 * 2 * 4 * 32];
// h fp16 (single) B-frag order: [parity2][w8][kt8][nt8][lane32][rb2]
__device__ uint32_t g_hfrag[(size_t)2 * 32768];
// x fp16 (single) B-frag order: [t][w8][kt2][nt8][lane32][rb2] = 8192 u32/t
__device__ uint32_t g_xfrag[(size_t)T_ * 8192];
__device__ int g_flag[(size_t)T_ * 128];

// ---------------- helpers ----------------
__device__ __forceinline__ ull pkdup(float v) {
    ull r; asm("mov.b64 %0, {%1, %1};" : "=l"(r) : "r"(__float_as_uint(v))); return r;
}
__device__ __forceinline__ void fma2(ull& d, ull a, ull b) {
    asm("fma.rn.f32x2 %0, %1, %2, %0;" : "+l"(d) : "l"(a), "l"(b));
}
__device__ __forceinline__ float lo2(ull v) { return __uint_as_float((unsigned)v); }
__device__ __forceinline__ float hi2(ull v) { return __uint_as_float((unsigned)(v >> 32)); }
__device__ __forceinline__ float sigf(float x) { return 1.0f / (1.0f + expf(-x)); }
__device__ __forceinline__ float tanh_acc(float x) {
    float ax = fabsf(x), e = expf(-2.0f * ax);
    return copysignf((1.0f - e) / (1.0f + e), x);
}
__device__ __forceinline__ uint2 ldg_cg2(const uint32_t* p) {
    uint2 v;
    asm volatile("ld.global.cg.v2.u32 {%0,%1}, [%2];" : "=r"(v.x), "=r"(v.y) : "l"(p));
    return v;
}
__device__ __forceinline__ void mma_f16(float& d0, float& d1, float& d2, float& d3,
                                        uint32_t a0, uint32_t a1, uint32_t a2,
                                        uint32_t a3, uint32_t b0, uint32_t b1) {
    asm volatile(
        "mma.sync.aligned.m16n8k16.row.col.f32.f16.f16.f32 "
        "{%0,%1,%2,%3},{%4,%5,%6,%7},{%8,%9},{%0,%1,%2,%3};"
        : "+f"(d0), "+f"(d1), "+f"(d2), "+f"(d3)
        : "r"(a0), "r"(a1), "r"(a2), "r"(a3), "r"(b0), "r"(b1));
}
__device__ __forceinline__ uint32_t h16bits(float v) {
    return (uint32_t)__half_as_ushort(__float2half(v));
}
__device__ __forceinline__ uint32_t split_word16(float v0, float v1, int split) {
    if (split == 0) return h16bits(v0) | (h16bits(v1) << 16);
    float h0 = __half2float(__float2half(v0));
    float h1 = __half2float(__float2half(v1));
    return h16bits(v0 - h0) | (h16bits(v1 - h1) << 16);
}
__device__ __forceinline__ uint32_t pack16(float v0, float v1) {
    return h16bits(v0) | (h16bits(v1) << 16);
}

// ---------------- prep kernels ----------------
__global__ void prep_wfrag(const float* __restrict__ wf, const float* __restrict__ wi,
                           const float* __restrict__ wo, const float* __restrict__ wc) {
    const int total = 128 << 15;
    for (int idx = blockIdx.x * blockDim.x + threadIdx.x; idx < total;
         idx += gridDim.x * blockDim.x) {
        int lane = idx & 31, reg = (idx >> 5) & 3, split = (idx >> 7) & 1;
        int kt = (idx >> 8) & 7, mt = (idx >> 11) & 1, w = (idx >> 12) & 7;
        int cta = idx >> 15;
        int r = mt * 16 + (lane >> 2) + (reg & 1) * 8;
        int k = w * 128 + kt * 16 + (lane & 3) * 2 + (reg >> 1) * 8;
        int g = r >> 3, jj = r & 7, j = cta * 8 + jj;
        const float* W = (g == 0) ? wf : (g == 1) ? wi : (g == 2) ? wo : wc;
        g_Wfrag[idx] =
            split_word16(W[(size_t)j * H_ + k], W[(size_t)j * H_ + k + 1], split);
    }
}
__global__ void prep_wxfrag(const float* __restrict__ wf, const float* __restrict__ wi,
                            const float* __restrict__ wo, const float* __restrict__ wc) {
    const int total = 128 << 13;
    for (int idx = blockIdx.x * blockDim.x + threadIdx.x; idx < total;
         idx += gridDim.x * blockDim.x) {
        int lane = idx & 31, reg = (idx >> 5) & 3, split = (idx >> 7) & 1;
        int kt = (idx >> 8) & 1, mt = (idx >> 9) & 1, w = (idx >> 10) & 7;
        int cta = idx >> 13;
        int r = mt * 16 + (lane >> 2) + (reg & 1) * 8;
        int k = w * 32 + kt * 16 + (lane & 3) * 2 + (reg >> 1) * 8;
        int g = r >> 3, jj = r & 7, j = cta * 8 + jj;
        const float* W = (g == 0) ? wf : (g == 1) ? wi : (g == 2) ? wo : wc;
        g_WXfrag[idx] =
            split_word16(W[(size_t)j * F_ + k], W[(size_t)j * F_ + k + 1], split);
    }
}
__global__ void prep_xfrag(const float* __restrict__ x) {
    const int total = T_ << 13;
    for (int idx = blockIdx.x * blockDim.x + threadIdx.x; idx < total;
         idx += gridDim.x * blockDim.x) {
        int rb = idx & 1, lane = (idx >> 1) & 31;
        int nt = (idx >> 6) & 7, kt = (idx >> 9) & 1, w = (idx >> 10) & 7;
        int t = idx >> 13;
        int b = nt * 8 + (lane >> 2);
        int f = w * 32 + kt * 16 + rb * 8 + (lane & 3) * 2;
        const float* xp = x + ((size_t)t * B_ + b) * F_ + f;
        g_xfrag[idx] = pack16(xp[0], xp[1]);
    }
}
// prep_fc + flag zeroing merged so k_rec3 is the 6th launch (ncu -s 5 -c 1).
__global__ void prep_misc(const float* __restrict__ fco_w) {
    const int total = 9 * H_ * 32;
    for (int idx = blockIdx.x * blockDim.x + threadIdx.x; idx < total;
         idx += gridDim.x * blockDim.x) {
        int cc = idx & 31, k = (idx >> 5) & (H_ - 1), ct = idx >> 15;
        int c = ct * 32 + cc;
        g_FCpk[idx] = (c < C_) ? fco_w[(size_t)c * H_ + k] : 0.0f;
    }
    for (int i = blockIdx.x * blockDim.x + threadIdx.x; i < T_ * 128;
         i += gridDim.x * blockDim.x)
        g_flag[i] = 0;
}

// ---------------- SIMT GEMM core (kept for k_out) ----------------
template <int NK>
__device__ __forceinline__ void gemm_core(const float4* __restrict__ Ag,
                                          const float4* __restrict__ Bg,
                                          float4 (*sA)[256], float4 (*sB)[512],
                                          ull (&acc)[4][2]) {
    const int tid = threadIdx.x, tn = tid >> 4, tb = tid & 15;
    float4 ra0, ra1, rb0, rb1, rb2, rb3;
    ra0 = Ag[tid]; ra1 = Ag[tid + 128];
    rb0 = Bg[tid]; rb1 = Bg[tid + 128]; rb2 = Bg[tid + 256]; rb3 = Bg[tid + 384];
    sA[0][tid] = ra0; sA[0][tid + 128] = ra1;
    sB[0][tid] = rb0; sB[0][tid + 128] = rb1;
    sB[0][tid + 256] = rb2; sB[0][tid + 384] = rb3;
    __syncthreads();
#pragma unroll 1
    for (int ch = 0; ch < NK; ++ch) {
        const int cur = ch & 1, nxt = cur ^ 1;
        if (ch + 1 < NK) {
            const float4* An = Ag + (size_t)(ch + 1) * 256;
            const float4* Bn = Bg + (size_t)(ch + 1) * 512;
            ra0 = An[tid]; ra1 = An[tid + 128];
            rb0 = Bn[tid]; rb1 = Bn[tid + 128];
            rb2 = Bn[tid + 256]; rb3 = Bn[tid + 384];
        }
        const float4* A = sA[cur];
        const float4* Bv = sB[cur];
#pragma unroll
        for (int kk = 0; kk < 32; ++kk) {
            float4 a = A[kk * 8 + tn];
            const ull* bp = reinterpret_cast<const ull*>(&Bv[kk * 16 + tb]);
            ull b0 = bp[0], b1 = bp[1];
            ull a0 = pkdup(a.x), a1 = pkdup(a.y), a2 = pkdup(a.z), a3 = pkdup(a.w);
            fma2(acc[0][0], a0, b0); fma2(acc[0][1], a0, b1);
            fma2(acc[1][0], a1, b0); fma2(acc[1][1], a1, b1);
            fma2(acc[2][0], a2, b0); fma2(acc[2][1], a2, b1);
            fma2(acc[3][0], a3, b0); fma2(acc[3][1], a3, b1);
        }
        __syncthreads();
        if (ch + 1 < NK) {
            sA[nxt][tid] = ra0; sA[nxt][tid + 128] = ra1;
            sB[nxt][tid] = rb0; sB[nxt][tid + 128] = rb1;
            sB[nxt][tid + 256] = rb2; sB[nxt][tid + 384] = rb3;
            __syncthreads();
        }
    }
}

// ---------------- gates GEMM via mma.sync (fp16, 2 products) ----------------
#define SM_PART 0
#define SM_ZBUF 65536
#define REC_SMEM (65536 + 32 * 66 * 4)

__global__ void __launch_bounds__(256, 1) k_gates_mma(
    const float* __restrict__ bfp, const float* __restrict__ bip,
    const float* __restrict__ bop, const float* __restrict__ bcp) {
    extern __shared__ unsigned char sm[];
    float* part = reinterpret_cast<float*>(sm + SM_PART);
    float* zbuf = reinterpret_cast<float*>(sm + SM_ZBUF);
    const int tid = threadIdx.x, w = tid >> 5, lane = tid & 31;
    const int jt = blockIdx.x, ts = blockIdx.y;

    uint32_t A[2][2][2][4];
    {
        const uint32_t* src = g_WXfrag + ((size_t)jt * 8 + w) * 1024 + lane;
#pragma unroll
        for (int mt = 0; mt < 2; ++mt)
#pragma unroll
            for (int kt = 0; kt < 2; ++kt)
#pragma unroll
                for (int sp = 0; sp < 2; ++sp)
#pragma unroll
                    for (int rg = 0; rg < 4; ++rg)
                        A[mt][kt][sp][rg] =
                            src[((((mt * 2 + kt) * 2 + sp) * 4 + rg) << 5)];
    }
    const int jj = tid >> 5, b0 = (tid & 31) * 2, j = jt * 8 + jj;
    const float bfv = bfp[j], biv = bip[j], bov = bop[j], bcv = bcp[j];

#pragma unroll 1
    for (int tt = 0; tt < 64; ++tt) {
        const int t = ts * 64 + tt;
        const uint32_t* ximg = g_xfrag + ((size_t)t << 13);
        float D[2][8][4];
#pragma unroll
        for (int mt = 0; mt < 2; ++mt)
#pragma unroll
            for (int nt = 0; nt < 8; ++nt)
#pragma unroll
                for (int rg = 0; rg < 4; ++rg) D[mt][nt][rg] = 0.f;
#pragma unroll
        for (int kt = 0; kt < 2; ++kt) {
#pragma unroll
            for (int nt = 0; nt < 8; ++nt) {
                const uint32_t* bb = ximg + ((w * 2 + kt) * 8 + nt) * 64 + lane * 2;
                uint2 bh = *reinterpret_cast<const uint2*>(bb);
#pragma unroll
                for (int mt = 0; mt < 2; ++mt) {
                    mma_f16(D[mt][nt][0], D[mt][nt][1], D[mt][nt][2], D[mt][nt][3],
                            A[mt][kt][0][0], A[mt][kt][0][1], A[mt][kt][0][2],
                            A[mt][kt][0][3], bh.x, bh.y);
                    mma_f16(D[mt][nt][0], D[mt][nt][1], D[mt][nt][2], D[mt][nt][3],
                            A[mt][kt][1][0], A[mt][kt][1][1], A[mt][kt][1][2],
                            A[mt][kt][1][3], bh.x, bh.y);
                }
            }
        }
#pragma unroll
        for (int mt = 0; mt < 2; ++mt)
#pragma unroll
            for (int nt = 0; nt < 8; ++nt)
                *reinterpret_cast<float4*>(
                    part + ((((w * 2 + mt) * 8 + nt) * 32) + lane) * 4) =
                    make_float4(D[mt][nt][0], D[mt][nt][1], D[mt][nt][2], D[mt][nt][3]);
        __syncthreads();
#pragma unroll
        for (int cc = 0; cc < 2; ++cc) {
            int c = tid + cc * 256;
            int mt = c >> 8, nt = (c >> 5) & 7, ln = c & 31;
            float4 s = make_float4(0.f, 0.f, 0.f, 0.f);
#pragma unroll
            for (int ww = 0; ww < 8; ++ww) {
                float4 p = *reinterpret_cast<const float4*>(
                    part + ((((ww * 2 + mt) * 8 + nt) * 32) + ln) * 4);
                s.x += p.x; s.y += p.y; s.z += p.z; s.w += p.w;
            }
            int r = mt * 16 + (ln >> 2);
            int n = nt * 8 + (ln & 3) * 2;
            *reinterpret_cast<float2*>(zbuf + r * 66 + n) = make_float2(s.x, s.y);
            *reinterpret_cast<float2*>(zbuf + (r + 8) * 66 + n) = make_float2(s.z, s.w);
        }
        __syncthreads();
        float za[4][2];
#pragma unroll
        for (int g = 0; g < 4; ++g) {
            float2 v = *reinterpret_cast<const float2*>(zbuf + (g * 8 + jj) * 66 + b0);
            za[g][0] = v.x; za[g][1] = v.y;
        }
        float4* G = reinterpret_cast<float4*>(g_gates) + ((size_t)t * H_ + j) * 64 + b0;
        G[0] = make_float4(za[0][0] + bfv, za[1][0] + biv, za[2][0] + bov, za[3][0] + bcv);
        G[1] = make_float4(za[0][1] + bfv, za[1][1] + biv, za[2][1] + bov, za[3][1] + bcv);
        __syncthreads();
    }
}

// ---------------- persistent mma.sync recurrence (fp16, B reg-pipelined) ----
__global__ void __launch_bounds__(256, 1) k_rec3() {
    extern __shared__ unsigned char sm[];
    float* part = reinterpret_cast<float*>(sm + SM_PART);
    float* zbuf = reinterpret_cast<float*>(sm + SM_ZBUF);

    const int tid = threadIdx.x, w = tid >> 5, lane = tid & 31;
    const int cta = blockIdx.x;

    uint32_t A[2][8][2][4];
    {
        const uint32_t* src = g_Wfrag + ((size_t)cta * 8 + w) * 4096 + lane;
#pragma unroll
        for (int mt = 0; mt < 2; ++mt)
#pragma unroll
            for (int kt = 0; kt < 8; ++kt)
#pragma unroll
                for (int sp = 0; sp < 2; ++sp)
#pragma unroll
                    for (int rg = 0; rg < 4; ++rg)
                        A[mt][kt][sp][rg] =
                            src[((((mt * 8 + kt) * 2 + sp) * 4 + rg) << 5)];
    }

    const int jj = tid >> 5, b0 = (tid & 31) * 2, j = cta * 8 + jj;
    float cst0 = 0.f, cst1 = 0.f;
    const int w_j = j >> 7, kt_j = (j >> 4) & 7, rb_j = (j >> 3) & 1;
    const int byte_in = (j & 1) * 2;
    const int l_j0 = ((b0 & 7) << 2) + ((j & 7) >> 1);
    const int l_j1 = (((b0 + 1) & 7) << 2) + ((j & 7) >> 1);

#pragma unroll 1
    for (int t = 0; t < T_; ++t) {
        const float4* G4 = reinterpret_cast<const float4*>(g_gates) +
                           ((size_t)t * H_ + j) * 64 + b0;
        float4 gx0 = G4[0], gx1 = G4[1];

        float zadd[4][2];
        if (t > 0) {
            {
                const int* f = g_flag + (t - 1) * 128 + w * 16 + (lane & 15);
                int v;
                do {
                    asm volatile("ld.acquire.gpu.global.b32 %0, [%1];"
                                 : "=r"(v) : "l"(f));
                } while (!v);
                __syncwarp();
            }

            float D[2][8][4];
#pragma unroll
            for (int mt = 0; mt < 2; ++mt)
#pragma unroll
                for (int nt = 0; nt < 8; ++nt)
#pragma unroll
                    for (int rg = 0; rg < 4; ++rg) D[mt][nt][rg] = 0.f;

            const uint32_t* himg = g_hfrag + (size_t)((t - 1) & 1) * 32768;

            // B fragments double-buffered in registers: kt+1 loads issued
            // before kt's mma burst so no L2 latency is exposed in the
            // mma stream.
            uint2 Breg[2][8];
#pragma unroll
            for (int nt = 0; nt < 8; ++nt)
                Breg[0][nt] = ldg_cg2(himg + ((w * 8 + 0) * 8 + nt) * 64 + lane * 2);
#pragma unroll
            for (int kt = 0; kt < 8; ++kt) {
                if (kt < 7) {
#pragma unroll
                    for (int nt = 0; nt < 8; ++nt)
                        Breg[(kt + 1) & 1][nt] = ldg_cg2(
                            himg + ((w * 8 + kt + 1) * 8 + nt) * 64 + lane * 2);
                }
#pragma unroll
                for (int nt = 0; nt < 8; ++nt) {
                    uint2 bh = Breg[kt & 1][nt];
#pragma unroll
                    for (int mt = 0; mt < 2; ++mt) {
                        mma_f16(D[mt][nt][0], D[mt][nt][1], D[mt][nt][2], D[mt][nt][3],
                                A[mt][kt][0][0], A[mt][kt][0][1], A[mt][kt][0][2],
                                A[mt][kt][0][3], bh.x, bh.y);
                        mma_f16(D[mt][nt][0], D[mt][nt][1], D[mt][nt][2], D[mt][nt][3],
                                A[mt][kt][1][0], A[mt][kt][1][1], A[mt][kt][1][2],
                                A[mt][kt][1][3], bh.x, bh.y);
                    }
                }
            }
#pragma unroll
            for (int mt = 0; mt < 2; ++mt)
#pragma unroll
                for (int nt = 0; nt < 8; ++nt)
                    *reinterpret_cast<float4*>(
                        part + ((((w * 2 + mt) * 8 + nt) * 32) + lane) * 4) =
                        make_float4(D[mt][nt][0], D[mt][nt][1], D[mt][nt][2],
                                    D[mt][nt][3]);
            __syncthreads();
#pragma unroll
            for (int cc = 0; cc < 2; ++cc) {
                int c = tid + cc * 256;
                int mt = c >> 8, nt = (c >> 5) & 7, ln = c & 31;
                float4 s = make_float4(0.f, 0.f, 0.f, 0.f);
#pragma unroll
                for (int ww = 0; ww < 8; ++ww) {
                    float4 p = *reinterpret_cast<const float4*>(
                        part + ((((ww * 2 + mt) * 8 + nt) * 32) + ln) * 4);
                    s.x += p.x; s.y += p.y; s.z += p.z; s.w += p.w;
                }
                int r = mt * 16 + (ln >> 2);
                int n = nt * 8 + (ln & 3) * 2;
                *reinterpret_cast<float2*>(zbuf + r * 66 + n) = make_float2(s.x, s.y);
                *reinterpret_cast<float2*>(zbuf + (r + 8) * 66 + n) =
                    make_float2(s.z, s.w);
            }
            __syncthreads();
#pragma unroll
            for (int g = 0; g < 4; ++g) {
                float2 v = *reinterpret_cast<const float2*>(zbuf + (g * 8 + jj) * 66 + b0);
                zadd[g][0] = v.x;
                zadd[g][1] = v.y;
            }
        } else {
#pragma unroll
            for (int g = 0; g < 4; ++g) zadd[g][0] = zadd[g][1] = 0.f;
        }

        float ft0 = sigf(gx0.x + zadd[0][0]), it0 = sigf(gx0.y + zadd[1][0]);
        float ot0 = sigf(gx0.z + zadd[2][0]);
        cst0 = it0 * tanh_acc(gx0.w + zadd[3][0]) + ft0 * cst0;
        float h0 = ot0 * tanh_acc(cst0);
        float ft1 = sigf(gx1.x + zadd[0][1]), it1 = sigf(gx1.y + zadd[1][1]);
        float ot1 = sigf(gx1.z + zadd[2][1]);
        cst1 = it1 * tanh_acc(gx1.w + zadd[3][1]) + ft1 * cst1;
        float h1 = ot1 * tanh_acc(cst1);

        *reinterpret_cast<float2*>(g_hT + ((size_t)t * H_ + j) * B_ + b0) =
            make_float2(h0, h1);
        {
            uint32_t* img = g_hfrag + (size_t)(t & 1) * 32768;
            const int nt = b0 >> 3;
            size_t base = ((w_j * 8 + kt_j) * 8 + nt) * 64;
            unsigned char* pH0 = (unsigned char*)(img + base + l_j0 * 2 + rb_j) + byte_in;
            unsigned char* pH1 = (unsigned char*)(img + base + l_j1 * 2 + rb_j) + byte_in;
            *(__half*)pH0 = __float2half(h0);
            *(__half*)pH1 = __float2half(h1);
        }
        __syncthreads();
        if (tid == 0) {
            asm volatile("st.release.gpu.global.b32 [%0], %1;"
                         :: "l"(g_flag + t * 128 + cta), "r"(1) : "memory");
        }
    }
}

// ---------------- output projection (SIMT, kept) ----------------
__global__ void k_out(const float* __restrict__ fco_b, float* __restrict__ out) {
    const int ct = blockIdx.x, t = blockIdx.y;
    __shared__ float4 sA[2][256];
    __shared__ float4 sB[2][512];
    ull acc[4][2] = {};
    const float4* Ag = reinterpret_cast<const float4*>(g_FCpk) + (size_t)ct * H_ * 8;
    const float4* Bg = reinterpret_cast<const float4*>(g_hT) + (size_t)t * H_ * 16;
    gemm_core<H_ / 32>(Ag, Bg, sA, sB, acc);
    const int tn = threadIdx.x >> 4, tb = threadIdx.x & 15, c0 = ct * 32 + tn * 4;
    float z[4][4];
#pragma unroll
    for (int r = 0; r < 4; ++r) {
        z[r][0] = lo2(acc[r][0]); z[r][1] = hi2(acc[r][0]);
        z[r][2] = lo2(acc[r][1]); z[r][3] = hi2(acc[r][1]);
    }
#pragma unroll
    for (int bb = 0; bb < 4; ++bb) {
        const int b = tb * 4 + bb;
        float* o = out + ((size_t)t * B_ + b) * C_;
#pragma unroll
        for (int ci = 0; ci < 4; ++ci) {
            const int c = c0 + ci;
            if (c < C_) o[c] = z[ci][bb] + fco_b[c];
        }
    }
}

// ---------------- launch ----------------
extern "C" void kernel_launch(void* const* d_in, const int* in_sizes, int n_in,
                              void* d_out, int out_size) {
    const float* x     = (const float*)d_in[0];
    const float* wfx_w = (const float*)d_in[1];
    const float* wfx_b = (const float*)d_in[2];
    const float* wix_w = (const float*)d_in[3];
    const float* wix_b = (const float*)d_in[4];
    const float* wox_w = (const float*)d_in[5];
    const float* wox_b = (const float*)d_in[6];
    const float* wcx_w = (const float*)d_in[7];
    const float* wcx_b = (const float*)d_in[8];
    const float* wfh_w = (const float*)d_in[9];
    const float* wih_w = (const float*)d_in[10];
    const float* woh_w = (const float*)d_in[11];
    const float* wch_w = (const float*)d_in[12];
    const float* fco_w = (const float*)d_in[13];
    const float* fco_b = (const float*)d_in[14];
    float* out = (float*)d_out;
    (void)in_sizes; (void)n_in; (void)out_size;

    cudaFuncSetAttribute(k_rec3, cudaFuncAttributeMaxDynamicSharedMemorySize,
                         REC_SMEM);
    cudaFuncSetAttribute(k_gates_mma, cudaFuncAttributeMaxDynamicSharedMemorySize,
                         REC_SMEM);

    // Launch order matters for ncu (-s 5 -c 1): k_rec3 is the 6th launch.
    prep_wfrag<<<8192, 256>>>(wfh_w, wih_w, woh_w, wch_w);
    prep_wxfrag<<<2048, 256>>>(wfx_w, wix_w, wox_w, wcx_w);
    prep_xfrag<<<4096, 256>>>(x);
    prep_misc<<<576, 256>>>(fco_w);

    k_gates_mma<<<dim3(128, 8), 256, REC_SMEM>>>(wfx_b, wix_b, wox_b, wcx_b);

    k_rec3<<<128, 256, REC_SMEM>>>();

    k_out<<<dim3(9, 512), 128>>>(fco_b, out);
}